// round 12
// baseline (speedup 1.0000x reference)
#include <cuda_runtime.h>
#include <cuda_bf16.h>
#include <cstdint>

#define NB 4096
#define MB 1024
#define BATCH 8
#define NPIX (BATCH*NB)   // 32768

// ---------------- scratch (bf16) ----------------
__device__ __nv_bfloat16 g_wt[192*256];            // [n][k] transposed Wg|Wf|Wh
__device__ __nv_bfloat16 g_wot[256*128];           // [n][k] transposed Wo
__device__ __nv_bfloat16 g_gb[(size_t)NPIX*32];    // g [row][32]
__device__ __nv_bfloat16 g_fp[BATCH*MB*32];        // f pooled [b*M][32]
__device__ __nv_bfloat16 g_ht[BATCH*128*MB];       // h pooled TRANSPOSED [b][c][m]
__device__ __nv_bfloat16 g_obf[(size_t)NPIX*128];  // attention out [row][128]

// ---------------- helpers ----------------
__device__ __forceinline__ uint32_t packbf(float lo, float hi) {
    __nv_bfloat162 h = __float22bfloat162_rn(make_float2(lo, hi));
    return *reinterpret_cast<uint32_t*>(&h);
}
__device__ __forceinline__ void mma_bf16(float* c,
    uint32_t a0, uint32_t a1, uint32_t a2, uint32_t a3,
    uint32_t b0, uint32_t b1)
{
    asm volatile(
        "mma.sync.aligned.m16n8k16.row.col.f32.bf16.bf16.f32 "
        "{%0,%1,%2,%3},{%4,%5,%6,%7},{%8,%9},{%0,%1,%2,%3};\n"
        : "+f"(c[0]), "+f"(c[1]), "+f"(c[2]), "+f"(c[3])
        : "r"(a0), "r"(a1), "r"(a2), "r"(a3), "r"(b0), "r"(b1));
}
__device__ __forceinline__ void ldm4(uint32_t& r0, uint32_t& r1, uint32_t& r2, uint32_t& r3,
                                     uint32_t addr)
{
    asm volatile("ldmatrix.sync.aligned.m8n8.x4.shared.b16 {%0,%1,%2,%3}, [%4];\n"
                 : "=r"(r0), "=r"(r1), "=r"(r2), "=r"(r3) : "r"(addr));
}
__device__ __forceinline__ void cp16(uint32_t smem_dst, const void* gsrc)
{
    asm volatile("cp.async.cg.shared.global [%0], [%1], 16;\n"
                 :: "r"(smem_dst), "l"(gsrc) : "memory");
}
__device__ __forceinline__ void cp_commit()
{
    asm volatile("cp.async.commit_group;\n" ::: "memory");
}
__device__ __forceinline__ void cp_wait1()
{
    asm volatile("cp.async.wait_group 1;\n" ::: "memory");
}
__device__ __forceinline__ void cp_wait0()
{
    asm volatile("cp.async.wait_group 0;\n" ::: "memory");
}

// ---------------- prep: transpose + convert weights ----------------
__global__ void prep_k(const float* __restrict__ Wf, const float* __restrict__ Wg,
                       const float* __restrict__ Wh, const float* __restrict__ Wo)
{
    int idx = blockIdx.x * 256 + threadIdx.x;
    if (idx < 192*256) {
        int n = idx >> 8, k = idx & 255;
        float v = (n < 32) ? Wg[k*32 + n] : (n < 64) ? Wf[k*32 + (n-32)] : Wh[k*128 + (n-64)];
        g_wt[idx] = __float2bfloat16(v);
    }
    if (idx < 256*128) {
        int n = idx >> 7, k = idx & 127;
        g_wot[idx] = __float2bfloat16(Wo[k*256 + n]);
    }
}

// ---------------- projection + fused 2x2 pooling (register-prefetch pipeline) ----------------
__global__ void __launch_bounds__(256) proj_k(const float* __restrict__ X,
    const float* __restrict__ bg, const float* __restrict__ bfv, const float* __restrict__ bh)
{
    __shared__ uint32_t psm[10624];
    uint32_t* Xs = psm;          // [128][20]
    uint32_t* Ws = psm + 2560;   // [192][20]
    uint32_t* Pf = psm;          // [128][17]  (pool phase)
    uint32_t* Ph = psm + 2176;   // [128][66]
    const int tid = threadIdx.x, lane = tid & 31, w = tid >> 5;
    const int gp = lane >> 2, tg = lane & 3, l8 = lane & 7, gq = lane >> 3;
    const int row0 = blockIdx.x * 128;

    float acc[24][4];
    #pragma unroll
    for (int j = 0; j < 24; j++)
        #pragma unroll
        for (int i = 0; i < 4; i++) acc[j][i] = 0.f;

    const uint32_t sX = (uint32_t)__cvta_generic_to_shared(Xs);
    const uint32_t sW = (uint32_t)__cvta_generic_to_shared(Ws);
    const uint32_t aOff = sX + ((16*w + l8 + 8*(gq&1))*40 + 8*(gq>>1))*2;
    const uint32_t bRowOff = (l8 + 8*(gq>>1))*40 + 8*(gq&1);

    const uint4* wsrc = (const uint4*)g_wt;

    float4 xr[4]; uint4 wr[3];
    #pragma unroll
    for (int t = 0; t < 4; t++) {
        int idx = t*256 + tid; int rr = idx >> 3, q = idx & 7;
        xr[t] = *(const float4*)(X + (size_t)(row0+rr)*256 + q*4);
    }
    #pragma unroll
    for (int t = 0; t < 3; t++) {
        int idx = t*256 + tid; int rr = idx >> 2, q = idx & 3;
        wr[t] = wsrc[(size_t)rr*32 + q];
    }

    for (int kc = 0; kc < 256; kc += 32) {
        #pragma unroll
        for (int t = 0; t < 4; t++) {
            int idx = t*256 + tid; int rr = idx >> 3, q = idx & 7;
            Xs[rr*20 + q*2]     = packbf(xr[t].x, xr[t].y);
            Xs[rr*20 + q*2 + 1] = packbf(xr[t].z, xr[t].w);
        }
        #pragma unroll
        for (int t = 0; t < 3; t++) {
            int idx = t*256 + tid; int rr = idx >> 2, q = idx & 3;
            *(uint4*)&Ws[rr*20 + q*4] = wr[t];
        }
        if (kc + 32 < 256) {
            #pragma unroll
            for (int t = 0; t < 4; t++) {
                int idx = t*256 + tid; int rr = idx >> 3, q = idx & 7;
                xr[t] = *(const float4*)(X + (size_t)(row0+rr)*256 + kc + 32 + q*4);
            }
            #pragma unroll
            for (int t = 0; t < 3; t++) {
                int idx = t*256 + tid; int rr = idx >> 2, q = idx & 3;
                wr[t] = wsrc[(size_t)rr*32 + ((kc+32)>>3) + q];
            }
        }
        __syncthreads();
        #pragma unroll
        for (int ks = 0; ks < 2; ks++) {
            uint32_t a0,a1,a2,a3;
            ldm4(a0,a1,a2,a3, aOff + ks*32);
            #pragma unroll
            for (int jp = 0; jp < 12; jp++) {
                uint32_t b0,b1,b2,b3;
                ldm4(b0,b1,b2,b3, sW + (16*jp*40 + bRowOff + ks*16)*2);
                mma_bf16(acc[2*jp],   a0,a1,a2,a3, b0,b1);
                mma_bf16(acc[2*jp+1], a0,a1,a2,a3, b2,b3);
            }
        }
        __syncthreads();
    }

    const int r0l = 16*w + gp, r1l = r0l + 8;
    const int r0g = row0 + r0l, r1g = row0 + r1l;
    uint32_t* gout = (uint32_t*)g_gb;
    #pragma unroll
    for (int j = 0; j < 24; j++) {
        int nb = 8*j, cp = nb + 2*tg;
        if (nb < 32) {
            float b0v = bg[cp], b1v = bg[cp+1];
            gout[(size_t)r0g*16 + (cp>>1)] = packbf(acc[j][0]+b0v, acc[j][1]+b1v);
            gout[(size_t)r1g*16 + (cp>>1)] = packbf(acc[j][2]+b0v, acc[j][3]+b1v);
        } else if (nb < 64) {
            int c = cp - 32;
            float b0v = bfv[c], b1v = bfv[c+1];
            Pf[r0l*17 + (c>>1)] = packbf(acc[j][0]+b0v, acc[j][1]+b1v);
            Pf[r1l*17 + (c>>1)] = packbf(acc[j][2]+b0v, acc[j][3]+b1v);
        } else {
            int c = cp - 64;
            float b0v = bh[c], b1v = bh[c+1];
            Ph[r0l*66 + (c>>1)] = packbf(acc[j][0]+b0v, acc[j][1]+b1v);
            Ph[r1l*66 + (c>>1)] = packbf(acc[j][2]+b0v, acc[j][3]+b1v);
        }
    }
    __syncthreads();

    const int b0i = row0 >> 12;
    const int tpair = (row0 & 4095) >> 7;
    for (int it = tid; it < 512; it += 256) {
        int c2 = it & 15, w2 = it >> 4;
        uint32_t u00 = Pf[(2*w2)*17 + c2];
        uint32_t u01 = Pf[(2*w2+1)*17 + c2];
        uint32_t u10 = Pf[(64+2*w2)*17 + c2];
        uint32_t u11 = Pf[(64+2*w2+1)*17 + c2];
        __nv_bfloat162 v = __hmax2(__hmax2(*(__nv_bfloat162*)&u00, *(__nv_bfloat162*)&u01),
                                   __hmax2(*(__nv_bfloat162*)&u10, *(__nv_bfloat162*)&u11));
        ((uint32_t*)g_fp)[((size_t)b0i*MB + tpair*32 + w2)*16 + c2] = *(uint32_t*)&v;
    }
    for (int it = tid; it < 1024; it += 256) {
        int u = it & 15, c2 = it >> 4;
        int w2a = 2*u, w2b = 2*u + 1;
        uint32_t a0 = Ph[(2*w2a)*66 + c2],    a1 = Ph[(2*w2a+1)*66 + c2];
        uint32_t a2 = Ph[(64+2*w2a)*66 + c2], a3 = Ph[(64+2*w2a+1)*66 + c2];
        __nv_bfloat162 pa = __hmax2(__hmax2(*(__nv_bfloat162*)&a0, *(__nv_bfloat162*)&a1),
                                    __hmax2(*(__nv_bfloat162*)&a2, *(__nv_bfloat162*)&a3));
        uint32_t b0u = Ph[(2*w2b)*66 + c2],    b1u = Ph[(2*w2b+1)*66 + c2];
        uint32_t b2u = Ph[(64+2*w2b)*66 + c2], b3u = Ph[(64+2*w2b+1)*66 + c2];
        __nv_bfloat162 pb = __hmax2(__hmax2(*(__nv_bfloat162*)&b0u, *(__nv_bfloat162*)&b1u),
                                    __hmax2(*(__nv_bfloat162*)&b2u, *(__nv_bfloat162*)&b3u));
        __nv_bfloat162 lo = __halves2bfloat162(__low2bfloat16(pa),  __low2bfloat16(pb));
        __nv_bfloat162 hi = __halves2bfloat162(__high2bfloat16(pa), __high2bfloat16(pb));
        size_t dst = ((size_t)(b0i*128 + 2*c2))*512 + tpair*16 + u;
        ((uint32_t*)g_ht)[dst]       = *(uint32_t*)&lo;
        ((uint32_t*)g_ht)[dst + 512] = *(uint32_t*)&hi;
    }
}

// ---------------- flash attention: 512 threads, warp-pair column split ----------------
// 16 warps: qw = w&7 (16-row q-stripe), ch = w>>3 (64-col output half).
// Both warps of a pair compute identical S/softmax; PV/O split by column half.
#define ATTN_SMEM_BYTES 80896

__global__ void __launch_bounds__(512) attn_k()
{
    extern __shared__ uint32_t dsm[];
    const int tid = threadIdx.x, lane = tid & 31, w = tid >> 5;
    const int qw = w & 7, ch = w >> 3;
    const int gp = lane >> 2, tg = lane & 3, l8 = lane & 7, gq = lane >> 3;
    const int b = blockIdx.x >> 5, q0 = (blockIdx.x & 31)*128;

    const uint32_t sBase = (uint32_t)__cvta_generic_to_shared(dsm);
    const uint32_t sG = sBase;
    uint32_t sF[3], sH[3];
    #pragma unroll
    for (int i = 0; i < 3; i++) {
        sF[i] = sBase + (2560 + i*1280)*4;
        sH[i] = sBase + (6400 + i*4608)*4;
    }

    const uint32_t* gsrc = (const uint32_t*)g_gb + ((size_t)b*NB + q0)*16;
    const uint32_t* fbase = (const uint32_t*)g_fp + (size_t)b*MB*16;
    const uint32_t* hbase = (const uint32_t*)g_ht + (size_t)b*128*512;

    // prefetch group 0: G + tile0; group 1: tile1
    {
        { int rr = tid >> 2, q4 = tid & 3;
          cp16(sG + (rr*20 + q4*4)*4, gsrc + (size_t)rr*16 + q4*4); }
        if (tid < 256) { int rr = tid >> 2, q4 = tid & 3;
          cp16(sF[0] + (rr*20 + q4*4)*4, fbase + (size_t)rr*16 + q4*4); }
        #pragma unroll
        for (int t = 0; t < 2; t++) {
            int idx = t*512 + tid; int rr = idx >> 3, q4 = idx & 7;
            cp16(sH[0] + (rr*36 + q4*4)*4, hbase + (size_t)rr*512 + q4*4);
        }
        cp_commit();
        if (tid < 256) { int rr = tid >> 2, q4 = tid & 3;
          cp16(sF[1] + (rr*20 + q4*4)*4, fbase + (size_t)(64+rr)*16 + q4*4); }
        #pragma unroll
        for (int t = 0; t < 2; t++) {
            int idx = t*512 + tid; int rr = idx >> 3, q4 = idx & 7;
            cp16(sH[1] + (rr*36 + q4*4)*4, hbase + (size_t)rr*512 + 32 + q4*4);
        }
        cp_commit();
    }

    const uint32_t aOff = sG + ((16*qw + l8 + 8*(gq&1))*40 + 8*(gq>>1))*2;
    const uint32_t bRow40 = (l8 + 8*(gq>>1))*40 + 8*(gq&1);
    const uint32_t bRow72 = (l8 + 8*(gq>>1))*72 + 8*(gq&1);

    float m0v = -1e30f, m1v = -1e30f, l0v = 0.f, l1v = 0.f;
    float o[8][4];
    #pragma unroll
    for (int j = 0; j < 8; j++)
        #pragma unroll
        for (int i = 0; i < 4; i++) o[j][i] = 0.f;

    #pragma unroll 1
    for (int kt = 0; kt < 16; kt++) {
        const int ib = kt % 3;
        cp_wait1();
        __syncthreads();

        {
            const int kt2 = kt + 2;
            if (kt2 < 16) {
                const int ib2 = kt2 % 3;
                if (tid < 256) { int rr = tid >> 2, q4 = tid & 3;
                  cp16(sF[ib2] + (rr*20 + q4*4)*4, fbase + (size_t)(kt2*64 + rr)*16 + q4*4); }
                #pragma unroll
                for (int t = 0; t < 2; t++) {
                    int idx = t*512 + tid; int hr = idx >> 3, hq = idx & 7;
                    cp16(sH[ib2] + (hr*36 + hq*4)*4, hbase + (size_t)hr*512 + kt2*32 + hq*4);
                }
            }
            cp_commit();
        }

        // S = G @ F^T  (duplicated across the warp pair)
        float s[8][4];
        #pragma unroll
        for (int j = 0; j < 8; j++)
            #pragma unroll
            for (int i = 0; i < 4; i++) s[j][i] = 0.f;
        #pragma unroll
        for (int ks = 0; ks < 2; ks++) {
            uint32_t a0,a1,a2,a3;
            ldm4(a0,a1,a2,a3, aOff + ks*32);
            #pragma unroll
            for (int jp = 0; jp < 4; jp++) {
                uint32_t b0,b1,b2,b3;
                ldm4(b0,b1,b2,b3, sF[ib] + (16*jp*40 + bRow40 + ks*16)*2);
                mma_bf16(s[2*jp],   a0,a1,a2,a3, b0,b1);
                mma_bf16(s[2*jp+1], a0,a1,a2,a3, b2,b3);
            }
        }

        // online softmax (identical in both warps of a pair)
        {
            float tm = -1e30f;
            #pragma unroll
            for (int j = 0; j < 8; j++) tm = fmaxf(tm, fmaxf(s[j][0], s[j][1]));
            tm = fmaxf(tm, __shfl_xor_sync(0xffffffffu, tm, 1));
            tm = fmaxf(tm, __shfl_xor_sync(0xffffffffu, tm, 2));
            float mn = fmaxf(m0v, tm);
            float corr = __expf(m0v - mn);
            m0v = mn;
            float rs = 0.f;
            #pragma unroll
            for (int j = 0; j < 8; j++) {
                s[j][0] = __expf(s[j][0] - mn);
                s[j][1] = __expf(s[j][1] - mn);
                rs += s[j][0] + s[j][1];
            }
            rs += __shfl_xor_sync(0xffffffffu, rs, 1);
            rs += __shfl_xor_sync(0xffffffffu, rs, 2);
            l0v = l0v * corr + rs;
            #pragma unroll
            for (int j = 0; j < 8; j++) { o[j][0] *= corr; o[j][1] *= corr; }
        }
        {
            float tm = -1e30f;
            #pragma unroll
            for (int j = 0; j < 8; j++) tm = fmaxf(tm, fmaxf(s[j][2], s[j][3]));
            tm = fmaxf(tm, __shfl_xor_sync(0xffffffffu, tm, 1));
            tm = fmaxf(tm, __shfl_xor_sync(0xffffffffu, tm, 2));
            float mn = fmaxf(m1v, tm);
            float corr = __expf(m1v - mn);
            m1v = mn;
            float rs = 0.f;
            #pragma unroll
            for (int j = 0; j < 8; j++) {
                s[j][2] = __expf(s[j][2] - mn);
                s[j][3] = __expf(s[j][3] - mn);
                rs += s[j][2] + s[j][3];
            }
            rs += __shfl_xor_sync(0xffffffffu, rs, 1);
            rs += __shfl_xor_sync(0xffffffffu, rs, 2);
            l1v = l1v * corr + rs;
            #pragma unroll
            for (int j = 0; j < 8; j++) { o[j][2] *= corr; o[j][3] *= corr; }
        }

        // P -> bf16 A fragments
        uint32_t pa[4][4];
        #pragma unroll
        for (int ks = 0; ks < 4; ks++) {
            pa[ks][0] = packbf(s[2*ks][0],   s[2*ks][1]);
            pa[ks][1] = packbf(s[2*ks][2],   s[2*ks][3]);
            pa[ks][2] = packbf(s[2*ks+1][0], s[2*ks+1][1]);
            pa[ks][3] = packbf(s[2*ks+1][2], s[2*ks+1][3]);
        }

        // O += P @ H  (this warp's 64-col half)
        #pragma unroll
        for (int jp = 0; jp < 4; jp++) {
            const uint32_t hoff = sH[ib] + (16*(4*ch + jp)*72 + bRow72)*2;
            #pragma unroll
            for (int ks = 0; ks < 4; ks++) {
                uint32_t b0,b1,b2,b3;
                ldm4(b0,b1,b2,b3, hoff + (ks*16)*2);
                mma_bf16(o[2*jp],   pa[ks][0],pa[ks][1],pa[ks][2],pa[ks][3], b0,b1);
                mma_bf16(o[2*jp+1], pa[ks][0],pa[ks][1],pa[ks][2],pa[ks][3], b2,b3);
            }
        }
    }

    // epilogue
    const float inv0 = 1.f / l0v, inv1 = 1.f / l1v;
    uint32_t* osink = (uint32_t*)g_obf;
    const int r0g = b*NB + q0 + 16*qw + gp, r1g = r0g + 8;
    #pragma unroll
    for (int j = 0; j < 8; j++) {
        osink[(size_t)r0g*64 + 4*(8*ch + j) + tg] = packbf(o[j][0]*inv0, o[j][1]*inv0);
        osink[(size_t)r1g*64 + 4*(8*ch + j) + tg] = packbf(o[j][2]*inv1, o[j][3]*inv1);
    }
}

// ---------------- out = gamma * (O @ Wo + bo) + x ----------------
// 64 rows x 128 cols per block; warp w: rows 16*(w&3), col half 64*(w>>2).
#define OUT_SMEM_BYTES ((64*68 + 128*68)*4)   // 52224

__global__ void __launch_bounds__(256,3) out_k(const float* __restrict__ x,
    const float* __restrict__ bo, const float* __restrict__ gamma,
    float* __restrict__ out)
{
    extern __shared__ uint32_t osm[];
    uint32_t* Os  = osm;             // [64][68]
    uint32_t* Wos = osm + 64*68;     // [128][68]
    const int tid = threadIdx.x, lane = tid & 31, w = tid >> 5;
    const int rw = w & 3, cw = w >> 2;
    const int gp = lane >> 2, tg = lane & 3, l8 = lane & 7, gq = lane >> 3;
    const int row0 = (blockIdx.x >> 1)*64, col0 = (blockIdx.x & 1)*128;

    const uint32_t sO = (uint32_t)__cvta_generic_to_shared(Os);
    const uint32_t sW = (uint32_t)__cvta_generic_to_shared(Wos);

    // O tile: 64 rows x 64 u32 (full K=128 bf16 per row)
    const uint32_t* osrc = (const uint32_t*)g_obf;
    #pragma unroll
    for (int t = 0; t < 4; t++) {
        int idx = t*256 + tid; int rr = idx >> 4, q4 = idx & 15;
        cp16(sO + (rr*68 + q4*4)*4, osrc + (size_t)(row0+rr)*64 + q4*4);
    }
    // W tile: 128 rows x 64 u32
    const uint32_t* wsrc = (const uint32_t*)g_wot;
    #pragma unroll
    for (int t = 0; t < 8; t++) {
        int idx = t*256 + tid; int rr = idx >> 4, q4 = idx & 15;
        cp16(sW + (rr*68 + q4*4)*4, wsrc + (size_t)(col0+rr)*64 + q4*4);
    }
    cp_commit();

    float acc[8][4];
    #pragma unroll
    for (int j = 0; j < 8; j++)
        #pragma unroll
        for (int i = 0; i < 4; i++) acc[j][i] = 0.f;

    const uint32_t aRowOff = (16*rw + l8 + 8*(gq&1))*136 + 8*(gq>>1);
    const uint32_t bRowOff = (l8 + 8*(gq>>1))*136 + 8*(gq&1);

    cp_wait0();
    __syncthreads();

    #pragma unroll
    for (int ks = 0; ks < 8; ks++) {
        uint32_t a0,a1,a2,a3;
        ldm4(a0,a1,a2,a3, sO + (aRowOff + ks*16)*2);
        #pragma unroll
        for (int jp = 0; jp < 4; jp++) {
            uint32_t b0,b1,b2,b3;
            ldm4(b0,b1,b2,b3, sW + (16*(4*cw + jp)*136 + bRowOff + ks*16)*2);
            mma_bf16(acc[2*jp],   a0,a1,a2,a3, b0,b1);
            mma_bf16(acc[2*jp+1], a0,a1,a2,a3, b2,b3);
        }
    }

    const float gm = gamma[0];
    const int r0g = row0 + 16*rw + gp, r1g = r0g + 8;
    const int colbase = col0 + 64*cw;
    #pragma unroll
    for (int j = 0; j < 8; j++) {
        int col = colbase + 8*j + 2*tg;
        float b0v = bo[col], b1v = bo[col+1];
        float2 xv0 = *(const float2*)(x + (size_t)r0g*256 + col);
        float2 ov0 = make_float2(gm*(acc[j][0]+b0v) + xv0.x, gm*(acc[j][1]+b1v) + xv0.y);
        *(float2*)(out + (size_t)r0g*256 + col) = ov0;
        float2 xv1 = *(const float2*)(x + (size_t)r1g*256 + col);
        float2 ov1 = make_float2(gm*(acc[j][2]+b0v) + xv1.x, gm*(acc[j][3]+b1v) + xv1.y);
        *(float2*)(out + (size_t)r1g*256 + col) = ov1;
    }
}

// ---------------- launch ----------------
extern "C" void kernel_launch(void* const* d_in, const int* in_sizes, int n_in,
                              void* d_out, int out_size)
{
    (void)in_sizes; (void)n_in; (void)out_size;
    const float* x     = (const float*)d_in[0];
    const float* Wf    = (const float*)d_in[1];
    const float* bfv   = (const float*)d_in[2];
    const float* Wg    = (const float*)d_in[3];
    const float* bg    = (const float*)d_in[4];
    const float* Wh    = (const float*)d_in[5];
    const float* bh    = (const float*)d_in[6];
    const float* Wo    = (const float*)d_in[7];
    const float* bo    = (const float*)d_in[8];
    const float* gamma = (const float*)d_in[9];
    float* out = (float*)d_out;

    static bool attr_set = false;
    if (!attr_set) {
        cudaFuncSetAttribute(attn_k, cudaFuncAttributeMaxDynamicSharedMemorySize,
                             ATTN_SMEM_BYTES);
        cudaFuncSetAttribute(out_k, cudaFuncAttributeMaxDynamicSharedMemorySize,
                             OUT_SMEM_BYTES);
        attr_set = true;
    }

    prep_k<<<192, 256>>>(Wf, Wg, Wh, Wo);
    proj_k<<<NPIX/128, 256>>>(x, bg, bfv, bh);
    attn_k<<<NPIX/128, 512, ATTN_SMEM_BYTES>>>();
    out_k<<<(NPIX/64)*2, 256, OUT_SMEM_BYTES>>>(x, bo, gamma, out);
}

// round 13
// speedup vs baseline: 1.1010x; 1.1010x over previous
#include <cuda_runtime.h>
#include <cuda_bf16.h>
#include <cstdint>

#define NB 4096
#define MB 1024
#define BATCH 8
#define NPIX (BATCH*NB)   // 32768

// ---------------- scratch (bf16) ----------------
__device__ __nv_bfloat16 g_wt[192*256];            // [n][k] transposed Wg|Wf|Wh
__device__ __nv_bfloat16 g_wot[256*128];           // [n][k] transposed Wo
__device__ __nv_bfloat16 g_gb[(size_t)NPIX*32];    // g [row][32]
__device__ __nv_bfloat16 g_fp[BATCH*MB*32];        // f pooled [b*M][32]
__device__ __nv_bfloat16 g_ht[BATCH*128*MB];       // h pooled TRANSPOSED [b][c][m]
__device__ __nv_bfloat16 g_obf[(size_t)NPIX*128];  // attention out [row][128]

// ---------------- helpers ----------------
__device__ __forceinline__ uint32_t packbf(float lo, float hi) {
    __nv_bfloat162 h = __float22bfloat162_rn(make_float2(lo, hi));
    return *reinterpret_cast<uint32_t*>(&h);
}
__device__ __forceinline__ void mma_bf16(float* c,
    uint32_t a0, uint32_t a1, uint32_t a2, uint32_t a3,
    uint32_t b0, uint32_t b1)
{
    asm volatile(
        "mma.sync.aligned.m16n8k16.row.col.f32.bf16.bf16.f32 "
        "{%0,%1,%2,%3},{%4,%5,%6,%7},{%8,%9},{%0,%1,%2,%3};\n"
        : "+f"(c[0]), "+f"(c[1]), "+f"(c[2]), "+f"(c[3])
        : "r"(a0), "r"(a1), "r"(a2), "r"(a3), "r"(b0), "r"(b1));
}
__device__ __forceinline__ void ldm4(uint32_t& r0, uint32_t& r1, uint32_t& r2, uint32_t& r3,
                                     uint32_t addr)
{
    asm volatile("ldmatrix.sync.aligned.m8n8.x4.shared.b16 {%0,%1,%2,%3}, [%4];\n"
                 : "=r"(r0), "=r"(r1), "=r"(r2), "=r"(r3) : "r"(addr));
}
__device__ __forceinline__ void cp16(uint32_t smem_dst, const void* gsrc)
{
    asm volatile("cp.async.cg.shared.global [%0], [%1], 16;\n"
                 :: "r"(smem_dst), "l"(gsrc) : "memory");
}
__device__ __forceinline__ void cp_commit()
{
    asm volatile("cp.async.commit_group;\n" ::: "memory");
}
__device__ __forceinline__ void cp_wait1()
{
    asm volatile("cp.async.wait_group 1;\n" ::: "memory");
}
__device__ __forceinline__ void cp_wait0()
{
    asm volatile("cp.async.wait_group 0;\n" ::: "memory");
}

// ---------------- prep: transpose + convert weights ----------------
__global__ void prep_k(const float* __restrict__ Wf, const float* __restrict__ Wg,
                       const float* __restrict__ Wh, const float* __restrict__ Wo)
{
    int idx = blockIdx.x * 256 + threadIdx.x;
    if (idx < 192*256) {
        int n = idx >> 8, k = idx & 255;
        float v = (n < 32) ? Wg[k*32 + n] : (n < 64) ? Wf[k*32 + (n-32)] : Wh[k*128 + (n-64)];
        g_wt[idx] = __float2bfloat16(v);
    }
    if (idx < 256*128) {
        int n = idx >> 7, k = idx & 127;
        g_wot[idx] = __float2bfloat16(Wo[k*256 + n]);
    }
}

// ---------------- projection + fused 2x2 pooling (register-prefetch pipeline) ----------------
__global__ void __launch_bounds__(256) proj_k(const float* __restrict__ X,
    const float* __restrict__ bg, const float* __restrict__ bfv, const float* __restrict__ bh)
{
    __shared__ uint32_t psm[10624];
    uint32_t* Xs = psm;          // [128][20]
    uint32_t* Ws = psm + 2560;   // [192][20]
    uint32_t* Pf = psm;          // [128][17]  (pool phase)
    uint32_t* Ph = psm + 2176;   // [128][66]
    const int tid = threadIdx.x, lane = tid & 31, w = tid >> 5;
    const int gp = lane >> 2, tg = lane & 3, l8 = lane & 7, gq = lane >> 3;
    const int row0 = blockIdx.x * 128;

    float acc[24][4];
    #pragma unroll
    for (int j = 0; j < 24; j++)
        #pragma unroll
        for (int i = 0; i < 4; i++) acc[j][i] = 0.f;

    const uint32_t sX = (uint32_t)__cvta_generic_to_shared(Xs);
    const uint32_t sW = (uint32_t)__cvta_generic_to_shared(Ws);
    const uint32_t aOff = sX + ((16*w + l8 + 8*(gq&1))*40 + 8*(gq>>1))*2;
    const uint32_t bRowOff = (l8 + 8*(gq>>1))*40 + 8*(gq&1);

    const uint4* wsrc = (const uint4*)g_wt;

    float4 xr[4]; uint4 wr[3];
    #pragma unroll
    for (int t = 0; t < 4; t++) {
        int idx = t*256 + tid; int rr = idx >> 3, q = idx & 7;
        xr[t] = *(const float4*)(X + (size_t)(row0+rr)*256 + q*4);
    }
    #pragma unroll
    for (int t = 0; t < 3; t++) {
        int idx = t*256 + tid; int rr = idx >> 2, q = idx & 3;
        wr[t] = wsrc[(size_t)rr*32 + q];
    }

    for (int kc = 0; kc < 256; kc += 32) {
        #pragma unroll
        for (int t = 0; t < 4; t++) {
            int idx = t*256 + tid; int rr = idx >> 3, q = idx & 7;
            Xs[rr*20 + q*2]     = packbf(xr[t].x, xr[t].y);
            Xs[rr*20 + q*2 + 1] = packbf(xr[t].z, xr[t].w);
        }
        #pragma unroll
        for (int t = 0; t < 3; t++) {
            int idx = t*256 + tid; int rr = idx >> 2, q = idx & 3;
            *(uint4*)&Ws[rr*20 + q*4] = wr[t];
        }
        if (kc + 32 < 256) {
            #pragma unroll
            for (int t = 0; t < 4; t++) {
                int idx = t*256 + tid; int rr = idx >> 3, q = idx & 7;
                xr[t] = *(const float4*)(X + (size_t)(row0+rr)*256 + kc + 32 + q*4);
            }
            #pragma unroll
            for (int t = 0; t < 3; t++) {
                int idx = t*256 + tid; int rr = idx >> 2, q = idx & 3;
                wr[t] = wsrc[(size_t)rr*32 + ((kc+32)>>3) + q];
            }
        }
        __syncthreads();
        #pragma unroll
        for (int ks = 0; ks < 2; ks++) {
            uint32_t a0,a1,a2,a3;
            ldm4(a0,a1,a2,a3, aOff + ks*32);
            #pragma unroll
            for (int jp = 0; jp < 12; jp++) {
                uint32_t b0,b1,b2,b3;
                ldm4(b0,b1,b2,b3, sW + (16*jp*40 + bRowOff + ks*16)*2);
                mma_bf16(acc[2*jp],   a0,a1,a2,a3, b0,b1);
                mma_bf16(acc[2*jp+1], a0,a1,a2,a3, b2,b3);
            }
        }
        __syncthreads();
    }

    const int r0l = 16*w + gp, r1l = r0l + 8;
    const int r0g = row0 + r0l, r1g = row0 + r1l;
    uint32_t* gout = (uint32_t*)g_gb;
    #pragma unroll
    for (int j = 0; j < 24; j++) {
        int nb = 8*j, cp = nb + 2*tg;
        if (nb < 32) {
            float b0v = bg[cp], b1v = bg[cp+1];
            gout[(size_t)r0g*16 + (cp>>1)] = packbf(acc[j][0]+b0v, acc[j][1]+b1v);
            gout[(size_t)r1g*16 + (cp>>1)] = packbf(acc[j][2]+b0v, acc[j][3]+b1v);
        } else if (nb < 64) {
            int c = cp - 32;
            float b0v = bfv[c], b1v = bfv[c+1];
            Pf[r0l*17 + (c>>1)] = packbf(acc[j][0]+b0v, acc[j][1]+b1v);
            Pf[r1l*17 + (c>>1)] = packbf(acc[j][2]+b0v, acc[j][3]+b1v);
        } else {
            int c = cp - 64;
            float b0v = bh[c], b1v = bh[c+1];
            Ph[r0l*66 + (c>>1)] = packbf(acc[j][0]+b0v, acc[j][1]+b1v);
            Ph[r1l*66 + (c>>1)] = packbf(acc[j][2]+b0v, acc[j][3]+b1v);
        }
    }
    __syncthreads();

    const int b0i = row0 >> 12;
    const int tpair = (row0 & 4095) >> 7;
    for (int it = tid; it < 512; it += 256) {
        int c2 = it & 15, w2 = it >> 4;
        uint32_t u00 = Pf[(2*w2)*17 + c2];
        uint32_t u01 = Pf[(2*w2+1)*17 + c2];
        uint32_t u10 = Pf[(64+2*w2)*17 + c2];
        uint32_t u11 = Pf[(64+2*w2+1)*17 + c2];
        __nv_bfloat162 v = __hmax2(__hmax2(*(__nv_bfloat162*)&u00, *(__nv_bfloat162*)&u01),
                                   __hmax2(*(__nv_bfloat162*)&u10, *(__nv_bfloat162*)&u11));
        ((uint32_t*)g_fp)[((size_t)b0i*MB + tpair*32 + w2)*16 + c2] = *(uint32_t*)&v;
    }
    for (int it = tid; it < 1024; it += 256) {
        int u = it & 15, c2 = it >> 4;
        int w2a = 2*u, w2b = 2*u + 1;
        uint32_t a0 = Ph[(2*w2a)*66 + c2],    a1 = Ph[(2*w2a+1)*66 + c2];
        uint32_t a2 = Ph[(64+2*w2a)*66 + c2], a3 = Ph[(64+2*w2a+1)*66 + c2];
        __nv_bfloat162 pa = __hmax2(__hmax2(*(__nv_bfloat162*)&a0, *(__nv_bfloat162*)&a1),
                                    __hmax2(*(__nv_bfloat162*)&a2, *(__nv_bfloat162*)&a3));
        uint32_t b0u = Ph[(2*w2b)*66 + c2],    b1u = Ph[(2*w2b+1)*66 + c2];
        uint32_t b2u = Ph[(64+2*w2b)*66 + c2], b3u = Ph[(64+2*w2b+1)*66 + c2];
        __nv_bfloat162 pb = __hmax2(__hmax2(*(__nv_bfloat162*)&b0u, *(__nv_bfloat162*)&b1u),
                                    __hmax2(*(__nv_bfloat162*)&b2u, *(__nv_bfloat162*)&b3u));
        __nv_bfloat162 lo = __halves2bfloat162(__low2bfloat16(pa),  __low2bfloat16(pb));
        __nv_bfloat162 hi = __halves2bfloat162(__high2bfloat16(pa), __high2bfloat16(pb));
        size_t dst = ((size_t)(b0i*128 + 2*c2))*512 + tpair*16 + u;
        ((uint32_t*)g_ht)[dst]       = *(uint32_t*)&lo;
        ((uint32_t*)g_ht)[dst + 512] = *(uint32_t*)&hi;
    }
}

// ---------------- flash attention (R7/R10 known-good 256-thread version) ----------------
#define ATTN_SMEM_BYTES 80896

__global__ void __launch_bounds__(256) attn_k()
{
    extern __shared__ uint32_t dsm[];
    const int tid = threadIdx.x, lane = tid & 31, w = tid >> 5;
    const int gp = lane >> 2, tg = lane & 3, l8 = lane & 7, gq = lane >> 3;
    const int b = blockIdx.x >> 5, q0 = (blockIdx.x & 31)*128;

    const uint32_t sBase = (uint32_t)__cvta_generic_to_shared(dsm);
    const uint32_t sG = sBase;
    uint32_t sF[3], sH[3];
    #pragma unroll
    for (int i = 0; i < 3; i++) {
        sF[i] = sBase + (2560 + i*1280)*4;
        sH[i] = sBase + (6400 + i*4608)*4;
    }

    const uint32_t* gsrc = (const uint32_t*)g_gb + ((size_t)b*NB + q0)*16;
    const uint32_t* fbase = (const uint32_t*)g_fp + (size_t)b*MB*16;
    const uint32_t* hbase = (const uint32_t*)g_ht + (size_t)b*128*512;

    {
        #pragma unroll
        for (int t = 0; t < 2; t++) {
            int idx = t*256 + tid; int rr = idx >> 2, q4 = idx & 3;
            cp16(sG + (rr*20 + q4*4)*4, gsrc + (size_t)rr*16 + q4*4);
        }
        { int rr = tid >> 2, q4 = tid & 3;
          cp16(sF[0] + (rr*20 + q4*4)*4, fbase + (size_t)rr*16 + q4*4); }
        #pragma unroll
        for (int t = 0; t < 4; t++) {
            int idx = t*256 + tid; int rr = idx >> 3, q4 = idx & 7;
            cp16(sH[0] + (rr*36 + q4*4)*4, hbase + (size_t)rr*512 + q4*4);
        }
        cp_commit();
        { int rr = tid >> 2, q4 = tid & 3;
          cp16(sF[1] + (rr*20 + q4*4)*4, fbase + (size_t)(64+rr)*16 + q4*4); }
        #pragma unroll
        for (int t = 0; t < 4; t++) {
            int idx = t*256 + tid; int rr = idx >> 3, q4 = idx & 7;
            cp16(sH[1] + (rr*36 + q4*4)*4, hbase + (size_t)rr*512 + 32 + q4*4);
        }
        cp_commit();
    }

    const uint32_t aOff = sG + ((16*w + l8 + 8*(gq&1))*40 + 8*(gq>>1))*2;
    const uint32_t bRow40 = (l8 + 8*(gq>>1))*40 + 8*(gq&1);
    const uint32_t bRow72 = (l8 + 8*(gq>>1))*72 + 8*(gq&1);

    float m0v = -1e30f, m1v = -1e30f, l0v = 0.f, l1v = 0.f;
    float o[16][4];
    #pragma unroll
    for (int j = 0; j < 16; j++)
        #pragma unroll
        for (int i = 0; i < 4; i++) o[j][i] = 0.f;

    #pragma unroll 1
    for (int kt = 0; kt < 16; kt++) {
        const int ib = kt % 3;
        cp_wait1();
        __syncthreads();

        {
            const int kt2 = kt + 2;
            if (kt2 < 16) {
                const int ib2 = kt2 % 3;
                int rr = tid >> 2, q4 = tid & 3;
                cp16(sF[ib2] + (rr*20 + q4*4)*4, fbase + (size_t)(kt2*64 + rr)*16 + q4*4);
                #pragma unroll
                for (int t = 0; t < 4; t++) {
                    int idx = t*256 + tid; int hr = idx >> 3, hq = idx & 7;
                    cp16(sH[ib2] + (hr*36 + hq*4)*4, hbase + (size_t)hr*512 + kt2*32 + hq*4);
                }
            }
            cp_commit();
        }

        float s[8][4];
        #pragma unroll
        for (int j = 0; j < 8; j++)
            #pragma unroll
            for (int i = 0; i < 4; i++) s[j][i] = 0.f;
        #pragma unroll
        for (int ks = 0; ks < 2; ks++) {
            uint32_t a0,a1,a2,a3;
            ldm4(a0,a1,a2,a3, aOff + ks*32);
            #pragma unroll
            for (int jp = 0; jp < 4; jp++) {
                uint32_t b0,b1,b2,b3;
                ldm4(b0,b1,b2,b3, sF[ib] + (16*jp*40 + bRow40 + ks*16)*2);
                mma_bf16(s[2*jp],   a0,a1,a2,a3, b0,b1);
                mma_bf16(s[2*jp+1], a0,a1,a2,a3, b2,b3);
            }
        }

        {
            float tm = -1e30f;
            #pragma unroll
            for (int j = 0; j < 8; j++) tm = fmaxf(tm, fmaxf(s[j][0], s[j][1]));
            tm = fmaxf(tm, __shfl_xor_sync(0xffffffffu, tm, 1));
            tm = fmaxf(tm, __shfl_xor_sync(0xffffffffu, tm, 2));
            float mn = fmaxf(m0v, tm);
            float corr = __expf(m0v - mn);
            m0v = mn;
            float rs = 0.f;
            #pragma unroll
            for (int j = 0; j < 8; j++) {
                s[j][0] = __expf(s[j][0] - mn);
                s[j][1] = __expf(s[j][1] - mn);
                rs += s[j][0] + s[j][1];
            }
            rs += __shfl_xor_sync(0xffffffffu, rs, 1);
            rs += __shfl_xor_sync(0xffffffffu, rs, 2);
            l0v = l0v * corr + rs;
            #pragma unroll
            for (int j = 0; j < 16; j++) { o[j][0] *= corr; o[j][1] *= corr; }
        }
        {
            float tm = -1e30f;
            #pragma unroll
            for (int j = 0; j < 8; j++) tm = fmaxf(tm, fmaxf(s[j][2], s[j][3]));
            tm = fmaxf(tm, __shfl_xor_sync(0xffffffffu, tm, 1));
            tm = fmaxf(tm, __shfl_xor_sync(0xffffffffu, tm, 2));
            float mn = fmaxf(m1v, tm);
            float corr = __expf(m1v - mn);
            m1v = mn;
            float rs = 0.f;
            #pragma unroll
            for (int j = 0; j < 8; j++) {
                s[j][2] = __expf(s[j][2] - mn);
                s[j][3] = __expf(s[j][3] - mn);
                rs += s[j][2] + s[j][3];
            }
            rs += __shfl_xor_sync(0xffffffffu, rs, 1);
            rs += __shfl_xor_sync(0xffffffffu, rs, 2);
            l1v = l1v * corr + rs;
            #pragma unroll
            for (int j = 0; j < 16; j++) { o[j][2] *= corr; o[j][3] *= corr; }
        }

        uint32_t pa[4][4];
        #pragma unroll
        for (int ks = 0; ks < 4; ks++) {
            pa[ks][0] = packbf(s[2*ks][0],   s[2*ks][1]);
            pa[ks][1] = packbf(s[2*ks][2],   s[2*ks][3]);
            pa[ks][2] = packbf(s[2*ks+1][0], s[2*ks+1][1]);
            pa[ks][3] = packbf(s[2*ks+1][2], s[2*ks+1][3]);
        }

        #pragma unroll
        for (int jp = 0; jp < 8; jp++) {
            #pragma unroll
            for (int ks = 0; ks < 4; ks++) {
                uint32_t b0,b1,b2,b3;
                ldm4(b0,b1,b2,b3, sH[ib] + (16*jp*72 + bRow72 + ks*16)*2);
                mma_bf16(o[2*jp],   pa[ks][0],pa[ks][1],pa[ks][2],pa[ks][3], b0,b1);
                mma_bf16(o[2*jp+1], pa[ks][0],pa[ks][1],pa[ks][2],pa[ks][3], b2,b3);
            }
        }
    }

    const float inv0 = 1.f / l0v, inv1 = 1.f / l1v;
    uint32_t* osink = (uint32_t*)g_obf;
    const int r0g = b*NB + q0 + 16*w + gp, r1g = r0g + 8;
    #pragma unroll
    for (int j = 0; j < 16; j++) {
        osink[(size_t)r0g*64 + 4*j + tg] = packbf(o[j][0]*inv0, o[j][1]*inv0);
        osink[(size_t)r1g*64 + 4*j + tg] = packbf(o[j][2]*inv1, o[j][3]*inv1);
    }
}

// ---------------- out = gamma * (O @ Wo + bo) + x  (split-K double-buffer) ----------------
// 64 rows x 128 cols per block. K=128 split: group A = bf16 cols 0..63 (q4 0..7),
// group B = cols 64..127 (q4 8..15). mma ks 0..3 consumes A, ks 4..7 consumes B.
#define OUT_SMEM_BYTES ((64*68 + 128*68)*4)   // 52224

__global__ void __launch_bounds__(256,3) out_k(const float* __restrict__ x,
    const float* __restrict__ bo, const float* __restrict__ gamma,
    float* __restrict__ out)
{
    extern __shared__ uint32_t osm[];
    uint32_t* Os  = osm;             // [64][68]
    uint32_t* Wos = osm + 64*68;     // [128][68]
    const int tid = threadIdx.x, lane = tid & 31, w = tid >> 5;
    const int rw = w & 3, cw = w >> 2;
    const int gp = lane >> 2, tg = lane & 3, l8 = lane & 7, gq = lane >> 3;
    const int row0 = (blockIdx.x >> 1)*64, col0 = (blockIdx.x & 1)*128;

    const uint32_t sO = (uint32_t)__cvta_generic_to_shared(Os);
    const uint32_t sW = (uint32_t)__cvta_generic_to_shared(Wos);

    const uint32_t* osrc = (const uint32_t*)g_obf;
    const uint32_t* wsrc = (const uint32_t*)g_wot;

    // group A: K bf16 0..63 (u32 q4 chunks 0..7)
    #pragma unroll
    for (int t = 0; t < 2; t++) {
        int idx = t*256 + tid; int rr = idx >> 3, q4 = idx & 7;
        cp16(sO + (rr*68 + q4*4)*4, osrc + (size_t)(row0+rr)*64 + q4*4);
    }
    #pragma unroll
    for (int t = 0; t < 4; t++) {
        int idx = t*256 + tid; int rr = idx >> 3, q4 = idx & 7;
        cp16(sW + (rr*68 + q4*4)*4, wsrc + (size_t)(col0+rr)*64 + q4*4);
    }
    cp_commit();
    // group B: K bf16 64..127 (u32 q4 chunks 8..15)
    #pragma unroll
    for (int t = 0; t < 2; t++) {
        int idx = t*256 + tid; int rr = idx >> 3, q4 = (idx & 7) + 8;
        cp16(sO + (rr*68 + q4*4)*4, osrc + (size_t)(row0+rr)*64 + q4*4);
    }
    #pragma unroll
    for (int t = 0; t < 4; t++) {
        int idx = t*256 + tid; int rr = idx >> 3, q4 = (idx & 7) + 8;
        cp16(sW + (rr*68 + q4*4)*4, wsrc + (size_t)(col0+rr)*64 + q4*4);
    }
    cp_commit();

    float acc[8][4];
    #pragma unroll
    for (int j = 0; j < 8; j++)
        #pragma unroll
        for (int i = 0; i < 4; i++) acc[j][i] = 0.f;

    const uint32_t aRowOff = (16*rw + l8 + 8*(gq&1))*136 + 8*(gq>>1);
    const uint32_t bRowOff = (l8 + 8*(gq>>1))*136 + 8*(gq&1);

    cp_wait1();        // group A resident
    __syncthreads();

    #pragma unroll
    for (int ks = 0; ks < 4; ks++) {
        uint32_t a0,a1,a2,a3;
        ldm4(a0,a1,a2,a3, sO + (aRowOff + ks*16)*2);
        #pragma unroll
        for (int jp = 0; jp < 4; jp++) {
            uint32_t b0,b1,b2,b3;
            ldm4(b0,b1,b2,b3, sW + (16*(4*cw + jp)*136 + bRowOff + ks*16)*2);
            mma_bf16(acc[2*jp],   a0,a1,a2,a3, b0,b1);
            mma_bf16(acc[2*jp+1], a0,a1,a2,a3, b2,b3);
        }
    }

    cp_wait0();        // group B resident
    __syncthreads();

    #pragma unroll
    for (int ks = 4; ks < 8; ks++) {
        uint32_t a0,a1,a2,a3;
        ldm4(a0,a1,a2,a3, sO + (aRowOff + ks*16)*2);
        #pragma unroll
        for (int jp = 0; jp < 4; jp++) {
            uint32_t b0,b1,b2,b3;
            ldm4(b0,b1,b2,b3, sW + (16*(4*cw + jp)*136 + bRowOff + ks*16)*2);
            mma_bf16(acc[2*jp],   a0,a1,a2,a3, b0,b1);
            mma_bf16(acc[2*jp+1], a0,a1,a2,a3, b2,b3);
        }
    }

    const float gm = gamma[0];
    const int r0g = row0 + 16*rw + gp, r1g = r0g + 8;
    const int colbase = col0 + 64*cw;
    #pragma unroll
    for (int j = 0; j < 8; j++) {
        int col = colbase + 8*j + 2*tg;
        float b0v = bo[col], b1v = bo[col+1];
        float2 xv0 = *(const float2*)(x + (size_t)r0g*256 + col);
        float2 ov0 = make_float2(gm*(acc[j][0]+b0v) + xv0.x, gm*(acc[j][1]+b1v) + xv0.y);
        *(float2*)(out + (size_t)r0g*256 + col) = ov0;
        float2 xv1 = *(const float2*)(x + (size_t)r1g*256 + col);
        float2 ov1 = make_float2(gm*(acc[j][2]+b0v) + xv1.x, gm*(acc[j][3]+b1v) + xv1.y);
        *(float2*)(out + (size_t)r1g*256 + col) = ov1;
    }
}

// ---------------- launch ----------------
extern "C" void kernel_launch(void* const* d_in, const int* in_sizes, int n_in,
                              void* d_out, int out_size)
{
    (void)in_sizes; (void)n_in; (void)out_size;
    const float* x     = (const float*)d_in[0];
    const float* Wf    = (const float*)d_in[1];
    const float* bfv   = (const float*)d_in[2];
    const float* Wg    = (const float*)d_in[3];
    const float* bg    = (const float*)d_in[4];
    const float* Wh    = (const float*)d_in[5];
    const float* bh    = (const float*)d_in[6];
    const float* Wo    = (const float*)d_in[7];
    const float* bo    = (const float*)d_in[8];
    const float* gamma = (const float*)d_in[9];
    float* out = (float*)d_out;

    static bool attr_set = false;
    if (!attr_set) {
        cudaFuncSetAttribute(attn_k, cudaFuncAttributeMaxDynamicSharedMemorySize,
                             ATTN_SMEM_BYTES);
        cudaFuncSetAttribute(out_k, cudaFuncAttributeMaxDynamicSharedMemorySize,
                             OUT_SMEM_BYTES);
        attr_set = true;
    }

    prep_k<<<192, 256>>>(Wf, Wg, Wh, Wo);
    proj_k<<<NPIX/128, 256>>>(x, bg, bfv, bh);
    attn_k<<<NPIX/128, 256, ATTN_SMEM_BYTES>>>();
    out_k<<<(NPIX/64)*2, 256, OUT_SMEM_BYTES>>>(x, bo, gamma, out);
}

// round 14
// speedup vs baseline: 1.1705x; 1.0631x over previous
#include <cuda_runtime.h>
#include <cuda_bf16.h>
#include <cstdint>

#define NB 4096
#define MB 1024
#define BATCH 8
#define NPIX (BATCH*NB)   // 32768

// ---------------- scratch (bf16) ----------------
__device__ __nv_bfloat16 g_wt[192*256];            // [n][k] transposed Wg|Wf|Wh
__device__ __nv_bfloat16 g_wot[256*128];           // [n][k] transposed Wo
__device__ __nv_bfloat16 g_gb[(size_t)NPIX*32];    // g [row][32]
__device__ __nv_bfloat16 g_fp[BATCH*MB*32];        // f pooled [b*M][32]
__device__ __nv_bfloat16 g_ht[BATCH*128*MB];       // h pooled TRANSPOSED [b][c][m]
__device__ __nv_bfloat16 g_obf[(size_t)NPIX*128];  // attention out [row][128]

// ---------------- helpers ----------------
__device__ __forceinline__ uint32_t packbf(float lo, float hi) {
    __nv_bfloat162 h = __float22bfloat162_rn(make_float2(lo, hi));
    return *reinterpret_cast<uint32_t*>(&h);
}
__device__ __forceinline__ void mma_bf16(float* c,
    uint32_t a0, uint32_t a1, uint32_t a2, uint32_t a3,
    uint32_t b0, uint32_t b1)
{
    asm volatile(
        "mma.sync.aligned.m16n8k16.row.col.f32.bf16.bf16.f32 "
        "{%0,%1,%2,%3},{%4,%5,%6,%7},{%8,%9},{%0,%1,%2,%3};\n"
        : "+f"(c[0]), "+f"(c[1]), "+f"(c[2]), "+f"(c[3])
        : "r"(a0), "r"(a1), "r"(a2), "r"(a3), "r"(b0), "r"(b1));
}
__device__ __forceinline__ void ldm4(uint32_t& r0, uint32_t& r1, uint32_t& r2, uint32_t& r3,
                                     uint32_t addr)
{
    asm volatile("ldmatrix.sync.aligned.m8n8.x4.shared.b16 {%0,%1,%2,%3}, [%4];\n"
                 : "=r"(r0), "=r"(r1), "=r"(r2), "=r"(r3) : "r"(addr));
}
__device__ __forceinline__ void cp16(uint32_t smem_dst, const void* gsrc)
{
    asm volatile("cp.async.cg.shared.global [%0], [%1], 16;\n"
                 :: "r"(smem_dst), "l"(gsrc) : "memory");
}
__device__ __forceinline__ void cp_commit()
{
    asm volatile("cp.async.commit_group;\n" ::: "memory");
}
__device__ __forceinline__ void cp_wait1()
{
    asm volatile("cp.async.wait_group 1;\n" ::: "memory");
}
__device__ __forceinline__ void cp_wait0()
{
    asm volatile("cp.async.wait_group 0;\n" ::: "memory");
}

// ---------------- prep: transpose + convert weights ----------------
__global__ void prep_k(const float* __restrict__ Wf, const float* __restrict__ Wg,
                       const float* __restrict__ Wh, const float* __restrict__ Wo)
{
    int idx = blockIdx.x * 256 + threadIdx.x;
    if (idx < 192*256) {
        int n = idx >> 8, k = idx & 255;
        float v = (n < 32) ? Wg[k*32 + n] : (n < 64) ? Wf[k*32 + (n-32)] : Wh[k*128 + (n-64)];
        g_wt[idx] = __float2bfloat16(v);
    }
    if (idx < 256*128) {
        int n = idx >> 7, k = idx & 127;
        g_wot[idx] = __float2bfloat16(Wo[k*256 + n]);
    }
}

// ---------------- projection + fused 2x2 pooling (register-prefetch pipeline) ----------------
__global__ void __launch_bounds__(256) proj_k(const float* __restrict__ X,
    const float* __restrict__ bg, const float* __restrict__ bfv, const float* __restrict__ bh)
{
    __shared__ uint32_t psm[10624];
    uint32_t* Xs = psm;          // [128][20]
    uint32_t* Ws = psm + 2560;   // [192][20]
    uint32_t* Pf = psm;          // [128][17]  (pool phase)
    uint32_t* Ph = psm + 2176;   // [128][66]
    const int tid = threadIdx.x, lane = tid & 31, w = tid >> 5;
    const int gp = lane >> 2, tg = lane & 3, l8 = lane & 7, gq = lane >> 3;
    const int row0 = blockIdx.x * 128;

    float acc[24][4];
    #pragma unroll
    for (int j = 0; j < 24; j++)
        #pragma unroll
        for (int i = 0; i < 4; i++) acc[j][i] = 0.f;

    const uint32_t sX = (uint32_t)__cvta_generic_to_shared(Xs);
    const uint32_t sW = (uint32_t)__cvta_generic_to_shared(Ws);
    const uint32_t aOff = sX + ((16*w + l8 + 8*(gq&1))*40 + 8*(gq>>1))*2;
    const uint32_t bRowOff = (l8 + 8*(gq>>1))*40 + 8*(gq&1);

    const uint4* wsrc = (const uint4*)g_wt;

    float4 xr[4]; uint4 wr[3];
    #pragma unroll
    for (int t = 0; t < 4; t++) {
        int idx = t*256 + tid; int rr = idx >> 3, q = idx & 7;
        xr[t] = *(const float4*)(X + (size_t)(row0+rr)*256 + q*4);
    }
    #pragma unroll
    for (int t = 0; t < 3; t++) {
        int idx = t*256 + tid; int rr = idx >> 2, q = idx & 3;
        wr[t] = wsrc[(size_t)rr*32 + q];
    }

    for (int kc = 0; kc < 256; kc += 32) {
        #pragma unroll
        for (int t = 0; t < 4; t++) {
            int idx = t*256 + tid; int rr = idx >> 3, q = idx & 7;
            Xs[rr*20 + q*2]     = packbf(xr[t].x, xr[t].y);
            Xs[rr*20 + q*2 + 1] = packbf(xr[t].z, xr[t].w);
        }
        #pragma unroll
        for (int t = 0; t < 3; t++) {
            int idx = t*256 + tid; int rr = idx >> 2, q = idx & 3;
            *(uint4*)&Ws[rr*20 + q*4] = wr[t];
        }
        if (kc + 32 < 256) {
            #pragma unroll
            for (int t = 0; t < 4; t++) {
                int idx = t*256 + tid; int rr = idx >> 3, q = idx & 7;
                xr[t] = *(const float4*)(X + (size_t)(row0+rr)*256 + kc + 32 + q*4);
            }
            #pragma unroll
            for (int t = 0; t < 3; t++) {
                int idx = t*256 + tid; int rr = idx >> 2, q = idx & 3;
                wr[t] = wsrc[(size_t)rr*32 + ((kc+32)>>3) + q];
            }
        }
        __syncthreads();
        #pragma unroll
        for (int ks = 0; ks < 2; ks++) {
            uint32_t a0,a1,a2,a3;
            ldm4(a0,a1,a2,a3, aOff + ks*32);
            #pragma unroll
            for (int jp = 0; jp < 12; jp++) {
                uint32_t b0,b1,b2,b3;
                ldm4(b0,b1,b2,b3, sW + (16*jp*40 + bRowOff + ks*16)*2);
                mma_bf16(acc[2*jp],   a0,a1,a2,a3, b0,b1);
                mma_bf16(acc[2*jp+1], a0,a1,a2,a3, b2,b3);
            }
        }
        __syncthreads();
    }

    const int r0l = 16*w + gp, r1l = r0l + 8;
    const int r0g = row0 + r0l, r1g = row0 + r1l;
    uint32_t* gout = (uint32_t*)g_gb;
    #pragma unroll
    for (int j = 0; j < 24; j++) {
        int nb = 8*j, cp = nb + 2*tg;
        if (nb < 32) {
            float b0v = bg[cp], b1v = bg[cp+1];
            gout[(size_t)r0g*16 + (cp>>1)] = packbf(acc[j][0]+b0v, acc[j][1]+b1v);
            gout[(size_t)r1g*16 + (cp>>1)] = packbf(acc[j][2]+b0v, acc[j][3]+b1v);
        } else if (nb < 64) {
            int c = cp - 32;
            float b0v = bfv[c], b1v = bfv[c+1];
            Pf[r0l*17 + (c>>1)] = packbf(acc[j][0]+b0v, acc[j][1]+b1v);
            Pf[r1l*17 + (c>>1)] = packbf(acc[j][2]+b0v, acc[j][3]+b1v);
        } else {
            int c = cp - 64;
            float b0v = bh[c], b1v = bh[c+1];
            Ph[r0l*66 + (c>>1)] = packbf(acc[j][0]+b0v, acc[j][1]+b1v);
            Ph[r1l*66 + (c>>1)] = packbf(acc[j][2]+b0v, acc[j][3]+b1v);
        }
    }
    __syncthreads();

    const int b0i = row0 >> 12;
    const int tpair = (row0 & 4095) >> 7;
    for (int it = tid; it < 512; it += 256) {
        int c2 = it & 15, w2 = it >> 4;
        uint32_t u00 = Pf[(2*w2)*17 + c2];
        uint32_t u01 = Pf[(2*w2+1)*17 + c2];
        uint32_t u10 = Pf[(64+2*w2)*17 + c2];
        uint32_t u11 = Pf[(64+2*w2+1)*17 + c2];
        __nv_bfloat162 v = __hmax2(__hmax2(*(__nv_bfloat162*)&u00, *(__nv_bfloat162*)&u01),
                                   __hmax2(*(__nv_bfloat162*)&u10, *(__nv_bfloat162*)&u11));
        ((uint32_t*)g_fp)[((size_t)b0i*MB + tpair*32 + w2)*16 + c2] = *(uint32_t*)&v;
    }
    for (int it = tid; it < 1024; it += 256) {
        int u = it & 15, c2 = it >> 4;
        int w2a = 2*u, w2b = 2*u + 1;
        uint32_t a0 = Ph[(2*w2a)*66 + c2],    a1 = Ph[(2*w2a+1)*66 + c2];
        uint32_t a2 = Ph[(64+2*w2a)*66 + c2], a3 = Ph[(64+2*w2a+1)*66 + c2];
        __nv_bfloat162 pa = __hmax2(__hmax2(*(__nv_bfloat162*)&a0, *(__nv_bfloat162*)&a1),
                                    __hmax2(*(__nv_bfloat162*)&a2, *(__nv_bfloat162*)&a3));
        uint32_t b0u = Ph[(2*w2b)*66 + c2],    b1u = Ph[(2*w2b+1)*66 + c2];
        uint32_t b2u = Ph[(64+2*w2b)*66 + c2], b3u = Ph[(64+2*w2b+1)*66 + c2];
        __nv_bfloat162 pb = __hmax2(__hmax2(*(__nv_bfloat162*)&b0u, *(__nv_bfloat162*)&b1u),
                                    __hmax2(*(__nv_bfloat162*)&b2u, *(__nv_bfloat162*)&b3u));
        __nv_bfloat162 lo = __halves2bfloat162(__low2bfloat16(pa),  __low2bfloat16(pb));
        __nv_bfloat162 hi = __halves2bfloat162(__high2bfloat16(pa), __high2bfloat16(pb));
        size_t dst = ((size_t)(b0i*128 + 2*c2))*512 + tpair*16 + u;
        ((uint32_t*)g_ht)[dst]       = *(uint32_t*)&lo;
        ((uint32_t*)g_ht)[dst + 512] = *(uint32_t*)&hi;
    }
}

// ---------------- flash attention: no-max softmax (scores bounded; exp safe in fp32) ----------------
#define ATTN_SMEM_BYTES 80896

__global__ void __launch_bounds__(256) attn_k()
{
    extern __shared__ uint32_t dsm[];
    const int tid = threadIdx.x, lane = tid & 31, w = tid >> 5;
    const int gp = lane >> 2, tg = lane & 3, l8 = lane & 7, gq = lane >> 3;
    const int b = blockIdx.x >> 5, q0 = (blockIdx.x & 31)*128;

    const uint32_t sBase = (uint32_t)__cvta_generic_to_shared(dsm);
    const uint32_t sG = sBase;
    uint32_t sF[3], sH[3];
    #pragma unroll
    for (int i = 0; i < 3; i++) {
        sF[i] = sBase + (2560 + i*1280)*4;
        sH[i] = sBase + (6400 + i*4608)*4;
    }

    const uint32_t* gsrc = (const uint32_t*)g_gb + ((size_t)b*NB + q0)*16;
    const uint32_t* fbase = (const uint32_t*)g_fp + (size_t)b*MB*16;
    const uint32_t* hbase = (const uint32_t*)g_ht + (size_t)b*128*512;

    {
        #pragma unroll
        for (int t = 0; t < 2; t++) {
            int idx = t*256 + tid; int rr = idx >> 2, q4 = idx & 3;
            cp16(sG + (rr*20 + q4*4)*4, gsrc + (size_t)rr*16 + q4*4);
        }
        { int rr = tid >> 2, q4 = tid & 3;
          cp16(sF[0] + (rr*20 + q4*4)*4, fbase + (size_t)rr*16 + q4*4); }
        #pragma unroll
        for (int t = 0; t < 4; t++) {
            int idx = t*256 + tid; int rr = idx >> 3, q4 = idx & 7;
            cp16(sH[0] + (rr*36 + q4*4)*4, hbase + (size_t)rr*512 + q4*4);
        }
        cp_commit();
        { int rr = tid >> 2, q4 = tid & 3;
          cp16(sF[1] + (rr*20 + q4*4)*4, fbase + (size_t)(64+rr)*16 + q4*4); }
        #pragma unroll
        for (int t = 0; t < 4; t++) {
            int idx = t*256 + tid; int rr = idx >> 3, q4 = idx & 7;
            cp16(sH[1] + (rr*36 + q4*4)*4, hbase + (size_t)rr*512 + 32 + q4*4);
        }
        cp_commit();
    }

    const uint32_t aOff = sG + ((16*w + l8 + 8*(gq&1))*40 + 8*(gq>>1))*2;
    const uint32_t bRow40 = (l8 + 8*(gq>>1))*40 + 8*(gq&1);
    const uint32_t bRow72 = (l8 + 8*(gq>>1))*72 + 8*(gq&1);

    float l0v = 0.f, l1v = 0.f;
    float o[16][4];
    #pragma unroll
    for (int j = 0; j < 16; j++)
        #pragma unroll
        for (int i = 0; i < 4; i++) o[j][i] = 0.f;

    #pragma unroll 1
    for (int kt = 0; kt < 16; kt++) {
        const int ib = kt % 3;
        cp_wait1();
        __syncthreads();

        {
            const int kt2 = kt + 2;
            if (kt2 < 16) {
                const int ib2 = kt2 % 3;
                int rr = tid >> 2, q4 = tid & 3;
                cp16(sF[ib2] + (rr*20 + q4*4)*4, fbase + (size_t)(kt2*64 + rr)*16 + q4*4);
                #pragma unroll
                for (int t = 0; t < 4; t++) {
                    int idx = t*256 + tid; int hr = idx >> 3, hq = idx & 7;
                    cp16(sH[ib2] + (hr*36 + hq*4)*4, hbase + (size_t)hr*512 + kt2*32 + hq*4);
                }
            }
            cp_commit();
        }

        float s[8][4];
        #pragma unroll
        for (int j = 0; j < 8; j++)
            #pragma unroll
            for (int i = 0; i < 4; i++) s[j][i] = 0.f;
        #pragma unroll
        for (int ks = 0; ks < 2; ks++) {
            uint32_t a0,a1,a2,a3;
            ldm4(a0,a1,a2,a3, aOff + ks*32);
            #pragma unroll
            for (int jp = 0; jp < 4; jp++) {
                uint32_t b0,b1,b2,b3;
                ldm4(b0,b1,b2,b3, sF[ib] + (16*jp*40 + bRow40 + ks*16)*2);
                mma_bf16(s[2*jp],   a0,a1,a2,a3, b0,b1);
                mma_bf16(s[2*jp+1], a0,a1,a2,a3, b2,b3);
            }
        }

        // ---- no-max softmax: P = exp(s); l accumulates row sums ----
        {
            float rs0 = 0.f, rs1 = 0.f;
            #pragma unroll
            for (int j = 0; j < 8; j++) {
                s[j][0] = __expf(s[j][0]);
                s[j][1] = __expf(s[j][1]);
                rs0 += s[j][0] + s[j][1];
                s[j][2] = __expf(s[j][2]);
                s[j][3] = __expf(s[j][3]);
                rs1 += s[j][2] + s[j][3];
            }
            rs0 += __shfl_xor_sync(0xffffffffu, rs0, 1);
            rs0 += __shfl_xor_sync(0xffffffffu, rs0, 2);
            rs1 += __shfl_xor_sync(0xffffffffu, rs1, 1);
            rs1 += __shfl_xor_sync(0xffffffffu, rs1, 2);
            l0v += rs0;
            l1v += rs1;
        }

        uint32_t pa[4][4];
        #pragma unroll
        for (int ks = 0; ks < 4; ks++) {
            pa[ks][0] = packbf(s[2*ks][0],   s[2*ks][1]);
            pa[ks][1] = packbf(s[2*ks][2],   s[2*ks][3]);
            pa[ks][2] = packbf(s[2*ks+1][0], s[2*ks+1][1]);
            pa[ks][3] = packbf(s[2*ks+1][2], s[2*ks+1][3]);
        }

        #pragma unroll
        for (int jp = 0; jp < 8; jp++) {
            #pragma unroll
            for (int ks = 0; ks < 4; ks++) {
                uint32_t b0,b1,b2,b3;
                ldm4(b0,b1,b2,b3, sH[ib] + (16*jp*72 + bRow72 + ks*16)*2);
                mma_bf16(o[2*jp],   pa[ks][0],pa[ks][1],pa[ks][2],pa[ks][3], b0,b1);
                mma_bf16(o[2*jp+1], pa[ks][0],pa[ks][1],pa[ks][2],pa[ks][3], b2,b3);
            }
        }
    }

    const float inv0 = 1.f / l0v, inv1 = 1.f / l1v;
    uint32_t* osink = (uint32_t*)g_obf;
    const int r0g = b*NB + q0 + 16*w + gp, r1g = r0g + 8;
    #pragma unroll
    for (int j = 0; j < 16; j++) {
        osink[(size_t)r0g*64 + 4*j + tg] = packbf(o[j][0]*inv0, o[j][1]*inv0);
        osink[(size_t)r1g*64 + 4*j + tg] = packbf(o[j][2]*inv1, o[j][3]*inv1);
    }
}

// ---------------- out = gamma * (O @ Wo + bo) + x  (split-K double-buffer) ----------------
#define OUT_SMEM_BYTES ((64*68 + 128*68)*4)   // 52224

__global__ void __launch_bounds__(256,3) out_k(const float* __restrict__ x,
    const float* __restrict__ bo, const float* __restrict__ gamma,
    float* __restrict__ out)
{
    extern __shared__ uint32_t osm[];
    uint32_t* Os  = osm;             // [64][68]
    uint32_t* Wos = osm + 64*68;     // [128][68]
    const int tid = threadIdx.x, lane = tid & 31, w = tid >> 5;
    const int rw = w & 3, cw = w >> 2;
    const int gp = lane >> 2, tg = lane & 3, l8 = lane & 7, gq = lane >> 3;
    const int row0 = (blockIdx.x >> 1)*64, col0 = (blockIdx.x & 1)*128;

    const uint32_t sO = (uint32_t)__cvta_generic_to_shared(Os);
    const uint32_t sW = (uint32_t)__cvta_generic_to_shared(Wos);

    const uint32_t* osrc = (const uint32_t*)g_obf;
    const uint32_t* wsrc = (const uint32_t*)g_wot;

    #pragma unroll
    for (int t = 0; t < 2; t++) {
        int idx = t*256 + tid; int rr = idx >> 3, q4 = idx & 7;
        cp16(sO + (rr*68 + q4*4)*4, osrc + (size_t)(row0+rr)*64 + q4*4);
    }
    #pragma unroll
    for (int t = 0; t < 4; t++) {
        int idx = t*256 + tid; int rr = idx >> 3, q4 = idx & 7;
        cp16(sW + (rr*68 + q4*4)*4, wsrc + (size_t)(col0+rr)*64 + q4*4);
    }
    cp_commit();
    #pragma unroll
    for (int t = 0; t < 2; t++) {
        int idx = t*256 + tid; int rr = idx >> 3, q4 = (idx & 7) + 8;
        cp16(sO + (rr*68 + q4*4)*4, osrc + (size_t)(row0+rr)*64 + q4*4);
    }
    #pragma unroll
    for (int t = 0; t < 4; t++) {
        int idx = t*256 + tid; int rr = idx >> 3, q4 = (idx & 7) + 8;
        cp16(sW + (rr*68 + q4*4)*4, wsrc + (size_t)(col0+rr)*64 + q4*4);
    }
    cp_commit();

    float acc[8][4];
    #pragma unroll
    for (int j = 0; j < 8; j++)
        #pragma unroll
        for (int i = 0; i < 4; i++) acc[j][i] = 0.f;

    const uint32_t aRowOff = (16*rw + l8 + 8*(gq&1))*136 + 8*(gq>>1);
    const uint32_t bRowOff = (l8 + 8*(gq>>1))*136 + 8*(gq&1);

    cp_wait1();
    __syncthreads();

    #pragma unroll
    for (int ks = 0; ks < 4; ks++) {
        uint32_t a0,a1,a2,a3;
        ldm4(a0,a1,a2,a3, sO + (aRowOff + ks*16)*2);
        #pragma unroll
        for (int jp = 0; jp < 4; jp++) {
            uint32_t b0,b1,b2,b3;
            ldm4(b0,b1,b2,b3, sW + (16*(4*cw + jp)*136 + bRowOff + ks*16)*2);
            mma_bf16(acc[2*jp],   a0,a1,a2,a3, b0,b1);
            mma_bf16(acc[2*jp+1], a0,a1,a2,a3, b2,b3);
        }
    }

    cp_wait0();
    __syncthreads();

    #pragma unroll
    for (int ks = 4; ks < 8; ks++) {
        uint32_t a0,a1,a2,a3;
        ldm4(a0,a1,a2,a3, sO + (aRowOff + ks*16)*2);
        #pragma unroll
        for (int jp = 0; jp < 4; jp++) {
            uint32_t b0,b1,b2,b3;
            ldm4(b0,b1,b2,b3, sW + (16*(4*cw + jp)*136 + bRowOff + ks*16)*2);
            mma_bf16(acc[2*jp],   a0,a1,a2,a3, b0,b1);
            mma_bf16(acc[2*jp+1], a0,a1,a2,a3, b2,b3);
        }
    }

    const float gm = gamma[0];
    const int r0g = row0 + 16*rw + gp, r1g = r0g + 8;
    const int colbase = col0 + 64*cw;
    #pragma unroll
    for (int j = 0; j < 8; j++) {
        int col = colbase + 8*j + 2*tg;
        float b0v = bo[col], b1v = bo[col+1];
        float2 xv0 = *(const float2*)(x + (size_t)r0g*256 + col);
        float2 ov0 = make_float2(gm*(acc[j][0]+b0v) + xv0.x, gm*(acc[j][1]+b1v) + xv0.y);
        *(float2*)(out + (size_t)r0g*256 + col) = ov0;
        float2 xv1 = *(const float2*)(x + (size_t)r1g*256 + col);
        float2 ov1 = make_float2(gm*(acc[j][2]+b0v) + xv1.x, gm*(acc[j][3]+b1v) + xv1.y);
        *(float2*)(out + (size_t)r1g*256 + col) = ov1;
    }
}

// ---------------- launch ----------------
extern "C" void kernel_launch(void* const* d_in, const int* in_sizes, int n_in,
                              void* d_out, int out_size)
{
    (void)in_sizes; (void)n_in; (void)out_size;
    const float* x     = (const float*)d_in[0];
    const float* Wf    = (const float*)d_in[1];
    const float* bfv   = (const float*)d_in[2];
    const float* Wg    = (const float*)d_in[3];
    const float* bg    = (const float*)d_in[4];
    const float* Wh    = (const float*)d_in[5];
    const float* bh    = (const float*)d_in[6];
    const float* Wo    = (const float*)d_in[7];
    const float* bo    = (const float*)d_in[8];
    const float* gamma = (const float*)d_in[9];
    float* out = (float*)d_out;

    static bool attr_set = false;
    if (!attr_set) {
        cudaFuncSetAttribute(attn_k, cudaFuncAttributeMaxDynamicSharedMemorySize,
                             ATTN_SMEM_BYTES);
        cudaFuncSetAttribute(out_k, cudaFuncAttributeMaxDynamicSharedMemorySize,
                             OUT_SMEM_BYTES);
        attr_set = true;
    }

    prep_k<<<192, 256>>>(Wf, Wg, Wh, Wo);
    proj_k<<<NPIX/128, 256>>>(x, bg, bfv, bh);
    attn_k<<<NPIX/128, 256, ATTN_SMEM_BYTES>>>();
    out_k<<<(NPIX/64)*2, 256, OUT_SMEM_BYTES>>>(x, bo, gamma, out);
}

// round 15
// speedup vs baseline: 1.1953x; 1.0213x over previous
#include <cuda_runtime.h>
#include <cuda_bf16.h>
#include <cstdint>

#define NB 4096
#define MB 1024
#define BATCH 8
#define NPIX (BATCH*NB)   // 32768

// ---------------- scratch (bf16) ----------------
__device__ __nv_bfloat16 g_wt[192*256];            // [n][k] transposed Wg|Wf|Wh
__device__ __nv_bfloat16 g_wot[256*128];           // [n][k] transposed Wo
__device__ __nv_bfloat16 g_gb[(size_t)NPIX*32];    // g [row][32]
__device__ __nv_bfloat16 g_fp[BATCH*MB*32];        // f pooled [b*M][32]
__device__ __nv_bfloat16 g_ht[BATCH*128*MB];       // h pooled TRANSPOSED [b][c][m]

// ---------------- helpers ----------------
__device__ __forceinline__ uint32_t packbf(float lo, float hi) {
    __nv_bfloat162 h = __float22bfloat162_rn(make_float2(lo, hi));
    return *reinterpret_cast<uint32_t*>(&h);
}
__device__ __forceinline__ void mma_bf16(float* c,
    uint32_t a0, uint32_t a1, uint32_t a2, uint32_t a3,
    uint32_t b0, uint32_t b1)
{
    asm volatile(
        "mma.sync.aligned.m16n8k16.row.col.f32.bf16.bf16.f32 "
        "{%0,%1,%2,%3},{%4,%5,%6,%7},{%8,%9},{%0,%1,%2,%3};\n"
        : "+f"(c[0]), "+f"(c[1]), "+f"(c[2]), "+f"(c[3])
        : "r"(a0), "r"(a1), "r"(a2), "r"(a3), "r"(b0), "r"(b1));
}
__device__ __forceinline__ void ldm4(uint32_t& r0, uint32_t& r1, uint32_t& r2, uint32_t& r3,
                                     uint32_t addr)
{
    asm volatile("ldmatrix.sync.aligned.m8n8.x4.shared.b16 {%0,%1,%2,%3}, [%4];\n"
                 : "=r"(r0), "=r"(r1), "=r"(r2), "=r"(r3) : "r"(addr));
}
__device__ __forceinline__ void cp16(uint32_t smem_dst, const void* gsrc)
{
    asm volatile("cp.async.cg.shared.global [%0], [%1], 16;\n"
                 :: "r"(smem_dst), "l"(gsrc) : "memory");
}
__device__ __forceinline__ void cp_commit()
{
    asm volatile("cp.async.commit_group;\n" ::: "memory");
}
__device__ __forceinline__ void cp_wait1()
{
    asm volatile("cp.async.wait_group 1;\n" ::: "memory");
}
__device__ __forceinline__ void cp_wait0()
{
    asm volatile("cp.async.wait_group 0;\n" ::: "memory");
}

// ---------------- prep: transpose + convert weights ----------------
__global__ void prep_k(const float* __restrict__ Wf, const float* __restrict__ Wg,
                       const float* __restrict__ Wh, const float* __restrict__ Wo)
{
    int idx = blockIdx.x * 256 + threadIdx.x;
    if (idx < 192*256) {
        int n = idx >> 8, k = idx & 255;
        float v = (n < 32) ? Wg[k*32 + n] : (n < 64) ? Wf[k*32 + (n-32)] : Wh[k*128 + (n-64)];
        g_wt[idx] = __float2bfloat16(v);
    }
    if (idx < 256*128) {
        int n = idx >> 7, k = idx & 127;
        g_wot[idx] = __float2bfloat16(Wo[k*256 + n]);
    }
}

// ---------------- projection + fused 2x2 pooling (register-prefetch pipeline) ----------------
__global__ void __launch_bounds__(256) proj_k(const float* __restrict__ X,
    const float* __restrict__ bg, const float* __restrict__ bfv, const float* __restrict__ bh)
{
    __shared__ uint32_t psm[10624];
    uint32_t* Xs = psm;          // [128][20]
    uint32_t* Ws = psm + 2560;   // [192][20]
    uint32_t* Pf = psm;          // [128][17]  (pool phase)
    uint32_t* Ph = psm + 2176;   // [128][66]
    const int tid = threadIdx.x, lane = tid & 31, w = tid >> 5;
    const int gp = lane >> 2, tg = lane & 3, l8 = lane & 7, gq = lane >> 3;
    const int row0 = blockIdx.x * 128;

    float acc[24][4];
    #pragma unroll
    for (int j = 0; j < 24; j++)
        #pragma unroll
        for (int i = 0; i < 4; i++) acc[j][i] = 0.f;

    const uint32_t sX = (uint32_t)__cvta_generic_to_shared(Xs);
    const uint32_t sW = (uint32_t)__cvta_generic_to_shared(Ws);
    const uint32_t aOff = sX + ((16*w + l8 + 8*(gq&1))*40 + 8*(gq>>1))*2;
    const uint32_t bRowOff = (l8 + 8*(gq>>1))*40 + 8*(gq&1);

    const uint4* wsrc = (const uint4*)g_wt;

    float4 xr[4]; uint4 wr[3];
    #pragma unroll
    for (int t = 0; t < 4; t++) {
        int idx = t*256 + tid; int rr = idx >> 3, q = idx & 7;
        xr[t] = *(const float4*)(X + (size_t)(row0+rr)*256 + q*4);
    }
    #pragma unroll
    for (int t = 0; t < 3; t++) {
        int idx = t*256 + tid; int rr = idx >> 2, q = idx & 3;
        wr[t] = wsrc[(size_t)rr*32 + q];
    }

    for (int kc = 0; kc < 256; kc += 32) {
        #pragma unroll
        for (int t = 0; t < 4; t++) {
            int idx = t*256 + tid; int rr = idx >> 3, q = idx & 7;
            Xs[rr*20 + q*2]     = packbf(xr[t].x, xr[t].y);
            Xs[rr*20 + q*2 + 1] = packbf(xr[t].z, xr[t].w);
        }
        #pragma unroll
        for (int t = 0; t < 3; t++) {
            int idx = t*256 + tid; int rr = idx >> 2, q = idx & 3;
            *(uint4*)&Ws[rr*20 + q*4] = wr[t];
        }
        if (kc + 32 < 256) {
            #pragma unroll
            for (int t = 0; t < 4; t++) {
                int idx = t*256 + tid; int rr = idx >> 3, q = idx & 7;
                xr[t] = *(const float4*)(X + (size_t)(row0+rr)*256 + kc + 32 + q*4);
            }
            #pragma unroll
            for (int t = 0; t < 3; t++) {
                int idx = t*256 + tid; int rr = idx >> 2, q = idx & 3;
                wr[t] = wsrc[(size_t)rr*32 + ((kc+32)>>3) + q];
            }
        }
        __syncthreads();
        #pragma unroll
        for (int ks = 0; ks < 2; ks++) {
            uint32_t a0,a1,a2,a3;
            ldm4(a0,a1,a2,a3, aOff + ks*32);
            #pragma unroll
            for (int jp = 0; jp < 12; jp++) {
                uint32_t b0,b1,b2,b3;
                ldm4(b0,b1,b2,b3, sW + (16*jp*40 + bRowOff + ks*16)*2);
                mma_bf16(acc[2*jp],   a0,a1,a2,a3, b0,b1);
                mma_bf16(acc[2*jp+1], a0,a1,a2,a3, b2,b3);
            }
        }
        __syncthreads();
    }

    const int r0l = 16*w + gp, r1l = r0l + 8;
    const int r0g = row0 + r0l, r1g = row0 + r1l;
    uint32_t* gout = (uint32_t*)g_gb;
    #pragma unroll
    for (int j = 0; j < 24; j++) {
        int nb = 8*j, cp = nb + 2*tg;
        if (nb < 32) {
            float b0v = bg[cp], b1v = bg[cp+1];
            gout[(size_t)r0g*16 + (cp>>1)] = packbf(acc[j][0]+b0v, acc[j][1]+b1v);
            gout[(size_t)r1g*16 + (cp>>1)] = packbf(acc[j][2]+b0v, acc[j][3]+b1v);
        } else if (nb < 64) {
            int c = cp - 32;
            float b0v = bfv[c], b1v = bfv[c+1];
            Pf[r0l*17 + (c>>1)] = packbf(acc[j][0]+b0v, acc[j][1]+b1v);
            Pf[r1l*17 + (c>>1)] = packbf(acc[j][2]+b0v, acc[j][3]+b1v);
        } else {
            int c = cp - 64;
            float b0v = bh[c], b1v = bh[c+1];
            Ph[r0l*66 + (c>>1)] = packbf(acc[j][0]+b0v, acc[j][1]+b1v);
            Ph[r1l*66 + (c>>1)] = packbf(acc[j][2]+b0v, acc[j][3]+b1v);
        }
    }
    __syncthreads();

    const int b0i = row0 >> 12;
    const int tpair = (row0 & 4095) >> 7;
    for (int it = tid; it < 512; it += 256) {
        int c2 = it & 15, w2 = it >> 4;
        uint32_t u00 = Pf[(2*w2)*17 + c2];
        uint32_t u01 = Pf[(2*w2+1)*17 + c2];
        uint32_t u10 = Pf[(64+2*w2)*17 + c2];
        uint32_t u11 = Pf[(64+2*w2+1)*17 + c2];
        __nv_bfloat162 v = __hmax2(__hmax2(*(__nv_bfloat162*)&u00, *(__nv_bfloat162*)&u01),
                                   __hmax2(*(__nv_bfloat162*)&u10, *(__nv_bfloat162*)&u11));
        ((uint32_t*)g_fp)[((size_t)b0i*MB + tpair*32 + w2)*16 + c2] = *(uint32_t*)&v;
    }
    for (int it = tid; it < 1024; it += 256) {
        int u = it & 15, c2 = it >> 4;
        int w2a = 2*u, w2b = 2*u + 1;
        uint32_t a0 = Ph[(2*w2a)*66 + c2],    a1 = Ph[(2*w2a+1)*66 + c2];
        uint32_t a2 = Ph[(64+2*w2a)*66 + c2], a3 = Ph[(64+2*w2a+1)*66 + c2];
        __nv_bfloat162 pa = __hmax2(__hmax2(*(__nv_bfloat162*)&a0, *(__nv_bfloat162*)&a1),
                                    __hmax2(*(__nv_bfloat162*)&a2, *(__nv_bfloat162*)&a3));
        uint32_t b0u = Ph[(2*w2b)*66 + c2],    b1u = Ph[(2*w2b+1)*66 + c2];
        uint32_t b2u = Ph[(64+2*w2b)*66 + c2], b3u = Ph[(64+2*w2b+1)*66 + c2];
        __nv_bfloat162 pb = __hmax2(__hmax2(*(__nv_bfloat162*)&b0u, *(__nv_bfloat162*)&b1u),
                                    __hmax2(*(__nv_bfloat162*)&b2u, *(__nv_bfloat162*)&b3u));
        __nv_bfloat162 lo = __halves2bfloat162(__low2bfloat16(pa),  __low2bfloat16(pb));
        __nv_bfloat162 hi = __halves2bfloat162(__high2bfloat16(pa), __high2bfloat16(pb));
        size_t dst = ((size_t)(b0i*128 + 2*c2))*512 + tpair*16 + u;
        ((uint32_t*)g_ht)[dst]       = *(uint32_t*)&lo;
        ((uint32_t*)g_ht)[dst + 512] = *(uint32_t*)&hi;
    }
}

// ---------------- fused attention + output projection ----------------
// Mainloop identical to R13 (no-max softmax). Epilogue: O (in registers) -> A-frags,
// Wo^T tile (256 rows x 128 k, pitch 68 u32) via cp.async into freed smem,
// two 128-col passes of O@Wo, write gamma*(.+bo)+x directly.
#define ATTN_SMEM_BYTES 80896

__global__ void __launch_bounds__(256) attn_k(const float* __restrict__ x,
    const float* __restrict__ bo, const float* __restrict__ gamma,
    float* __restrict__ out)
{
    extern __shared__ uint32_t dsm[];
    const int tid = threadIdx.x, lane = tid & 31, w = tid >> 5;
    const int gp = lane >> 2, tg = lane & 3, l8 = lane & 7, gq = lane >> 3;
    const int b = blockIdx.x >> 5, q0 = (blockIdx.x & 31)*128;

    const uint32_t sBase = (uint32_t)__cvta_generic_to_shared(dsm);
    const uint32_t sG = sBase;
    uint32_t sF[3], sH[3];
    #pragma unroll
    for (int i = 0; i < 3; i++) {
        sF[i] = sBase + (2560 + i*1280)*4;
        sH[i] = sBase + (6400 + i*4608)*4;
    }

    const uint32_t* gsrc = (const uint32_t*)g_gb + ((size_t)b*NB + q0)*16;
    const uint32_t* fbase = (const uint32_t*)g_fp + (size_t)b*MB*16;
    const uint32_t* hbase = (const uint32_t*)g_ht + (size_t)b*128*512;

    {
        #pragma unroll
        for (int t = 0; t < 2; t++) {
            int idx = t*256 + tid; int rr = idx >> 2, q4 = idx & 3;
            cp16(sG + (rr*20 + q4*4)*4, gsrc + (size_t)rr*16 + q4*4);
        }
        { int rr = tid >> 2, q4 = tid & 3;
          cp16(sF[0] + (rr*20 + q4*4)*4, fbase + (size_t)rr*16 + q4*4); }
        #pragma unroll
        for (int t = 0; t < 4; t++) {
            int idx = t*256 + tid; int rr = idx >> 3, q4 = idx & 7;
            cp16(sH[0] + (rr*36 + q4*4)*4, hbase + (size_t)rr*512 + q4*4);
        }
        cp_commit();
        { int rr = tid >> 2, q4 = tid & 3;
          cp16(sF[1] + (rr*20 + q4*4)*4, fbase + (size_t)(64+rr)*16 + q4*4); }
        #pragma unroll
        for (int t = 0; t < 4; t++) {
            int idx = t*256 + tid; int rr = idx >> 3, q4 = idx & 7;
            cp16(sH[1] + (rr*36 + q4*4)*4, hbase + (size_t)rr*512 + 32 + q4*4);
        }
        cp_commit();
    }

    const uint32_t aOff = sG + ((16*w + l8 + 8*(gq&1))*40 + 8*(gq>>1))*2;
    const uint32_t bRow40 = (l8 + 8*(gq>>1))*40 + 8*(gq&1);
    const uint32_t bRow72 = (l8 + 8*(gq>>1))*72 + 8*(gq&1);

    float l0v = 0.f, l1v = 0.f;
    float o[16][4];
    #pragma unroll
    for (int j = 0; j < 16; j++)
        #pragma unroll
        for (int i = 0; i < 4; i++) o[j][i] = 0.f;

    #pragma unroll 1
    for (int kt = 0; kt < 16; kt++) {
        const int ib = kt % 3;
        cp_wait1();
        __syncthreads();

        {
            const int kt2 = kt + 2;
            if (kt2 < 16) {
                const int ib2 = kt2 % 3;
                int rr = tid >> 2, q4 = tid & 3;
                cp16(sF[ib2] + (rr*20 + q4*4)*4, fbase + (size_t)(kt2*64 + rr)*16 + q4*4);
                #pragma unroll
                for (int t = 0; t < 4; t++) {
                    int idx = t*256 + tid; int hr = idx >> 3, hq = idx & 7;
                    cp16(sH[ib2] + (hr*36 + hq*4)*4, hbase + (size_t)hr*512 + kt2*32 + hq*4);
                }
            }
            cp_commit();
        }

        float s[8][4];
        #pragma unroll
        for (int j = 0; j < 8; j++)
            #pragma unroll
            for (int i = 0; i < 4; i++) s[j][i] = 0.f;
        #pragma unroll
        for (int ks = 0; ks < 2; ks++) {
            uint32_t a0,a1,a2,a3;
            ldm4(a0,a1,a2,a3, aOff + ks*32);
            #pragma unroll
            for (int jp = 0; jp < 4; jp++) {
                uint32_t b0,b1,b2,b3;
                ldm4(b0,b1,b2,b3, sF[ib] + (16*jp*40 + bRow40 + ks*16)*2);
                mma_bf16(s[2*jp],   a0,a1,a2,a3, b0,b1);
                mma_bf16(s[2*jp+1], a0,a1,a2,a3, b2,b3);
            }
        }

        // no-max softmax
        {
            float rs0 = 0.f, rs1 = 0.f;
            #pragma unroll
            for (int j = 0; j < 8; j++) {
                s[j][0] = __expf(s[j][0]);
                s[j][1] = __expf(s[j][1]);
                rs0 += s[j][0] + s[j][1];
                s[j][2] = __expf(s[j][2]);
                s[j][3] = __expf(s[j][3]);
                rs1 += s[j][2] + s[j][3];
            }
            rs0 += __shfl_xor_sync(0xffffffffu, rs0, 1);
            rs0 += __shfl_xor_sync(0xffffffffu, rs0, 2);
            rs1 += __shfl_xor_sync(0xffffffffu, rs1, 1);
            rs1 += __shfl_xor_sync(0xffffffffu, rs1, 2);
            l0v += rs0;
            l1v += rs1;
        }

        uint32_t pa[4][4];
        #pragma unroll
        for (int ks = 0; ks < 4; ks++) {
            pa[ks][0] = packbf(s[2*ks][0],   s[2*ks][1]);
            pa[ks][1] = packbf(s[2*ks][2],   s[2*ks][3]);
            pa[ks][2] = packbf(s[2*ks+1][0], s[2*ks+1][1]);
            pa[ks][3] = packbf(s[2*ks+1][2], s[2*ks+1][3]);
        }

        #pragma unroll
        for (int jp = 0; jp < 8; jp++) {
            #pragma unroll
            for (int ks = 0; ks < 4; ks++) {
                uint32_t b0,b1,b2,b3;
                ldm4(b0,b1,b2,b3, sH[ib] + (16*jp*72 + bRow72 + ks*16)*2);
                mma_bf16(o[2*jp],   pa[ks][0],pa[ks][1],pa[ks][2],pa[ks][3], b0,b1);
                mma_bf16(o[2*jp+1], pa[ks][0],pa[ks][1],pa[ks][2],pa[ks][3], b2,b3);
            }
        }
    }

    // ---- fused output projection ----
    // O -> bf16 A-fragments (identical values to the old g_obf bf16 store).
    const float inv0 = 1.f / l0v, inv1 = 1.f / l1v;
    uint32_t oa[8][4];
    #pragma unroll
    for (int ks = 0; ks < 8; ks++) {
        oa[ks][0] = packbf(o[2*ks][0]*inv0,   o[2*ks][1]*inv0);
        oa[ks][1] = packbf(o[2*ks][2]*inv1,   o[2*ks][3]*inv1);
        oa[ks][2] = packbf(o[2*ks+1][0]*inv0, o[2*ks+1][1]*inv0);
        oa[ks][3] = packbf(o[2*ks+1][2]*inv1, o[2*ks+1][3]*inv1);
    }

    __syncthreads();   // all warps done with F/H smem before Wo overwrite

    // Wo^T tile: 256 rows x 64 u32, pitch 68 (16 cp16 per thread)
    const uint32_t* wsrc = (const uint32_t*)g_wot;
    #pragma unroll
    for (int t = 0; t < 16; t++) {
        int idx = t*256 + tid; int rr = idx >> 4, q4 = idx & 15;
        cp16(sBase + (rr*68 + q4*4)*4, wsrc + (size_t)rr*64 + q4*4);
    }
    cp_commit();
    cp_wait0();
    __syncthreads();

    const uint32_t bRow136 = (l8 + 8*(gq>>1))*136 + 8*(gq&1);
    const float gm = gamma[0];
    const int r0g = b*NB + q0 + 16*w + gp, r1g = r0g + 8;

    #pragma unroll 1
    for (int pass = 0; pass < 2; pass++) {
        float acc[16][4];
        #pragma unroll
        for (int j = 0; j < 16; j++)
            #pragma unroll
            for (int i = 0; i < 4; i++) acc[j][i] = 0.f;

        #pragma unroll
        for (int ks = 0; ks < 8; ks++) {
            #pragma unroll
            for (int jp = 0; jp < 8; jp++) {
                uint32_t b0,b1,b2,b3;
                ldm4(b0,b1,b2,b3, sBase + ((128*pass + 16*jp)*136 + bRow136 + ks*16)*2);
                mma_bf16(acc[2*jp],   oa[ks][0],oa[ks][1],oa[ks][2],oa[ks][3], b0,b1);
                mma_bf16(acc[2*jp+1], oa[ks][0],oa[ks][1],oa[ks][2],oa[ks][3], b2,b3);
            }
        }

        #pragma unroll
        for (int j = 0; j < 16; j++) {
            int col = 128*pass + 8*j + 2*tg;
            float b0v = bo[col], b1v = bo[col+1];
            float2 xv0 = *(const float2*)(x + (size_t)r0g*256 + col);
            float2 ov0 = make_float2(gm*(acc[j][0]+b0v) + xv0.x, gm*(acc[j][1]+b1v) + xv0.y);
            *(float2*)(out + (size_t)r0g*256 + col) = ov0;
            float2 xv1 = *(const float2*)(x + (size_t)r1g*256 + col);
            float2 ov1 = make_float2(gm*(acc[j][2]+b0v) + xv1.x, gm*(acc[j][3]+b1v) + xv1.y);
            *(float2*)(out + (size_t)r1g*256 + col) = ov1;
        }
    }
}

// ---------------- launch ----------------
extern "C" void kernel_launch(void* const* d_in, const int* in_sizes, int n_in,
                              void* d_out, int out_size)
{
    (void)in_sizes; (void)n_in; (void)out_size;
    const float* x     = (const float*)d_in[0];
    const float* Wf    = (const float*)d_in[1];
    const float* bfv   = (const float*)d_in[2];
    const float* Wg    = (const float*)d_in[3];
    const float* bg    = (const float*)d_in[4];
    const float* Wh    = (const float*)d_in[5];
    const float* bh    = (const float*)d_in[6];
    const float* Wo    = (const float*)d_in[7];
    const float* bo    = (const float*)d_in[8];
    const float* gamma = (const float*)d_in[9];
    float* out = (float*)d_out;

    static bool attr_set = false;
    if (!attr_set) {
        cudaFuncSetAttribute(attn_k, cudaFuncAttributeMaxDynamicSharedMemorySize,
                             ATTN_SMEM_BYTES);
        attr_set = true;
    }

    prep_k<<<192, 256>>>(Wf, Wg, Wh, Wo);
    proj_k<<<NPIX/128, 256>>>(x, bg, bfv, bh);
    attn_k<<<NPIX/128, 256, ATTN_SMEM_BYTES>>>(x, bo, gamma, out);
}

// round 16
// speedup vs baseline: 1.2201x; 1.0207x over previous
#include <cuda_runtime.h>
#include <cuda_bf16.h>
#include <cstdint>

#define NB 4096
#define MB 1024
#define BATCH 8
#define NPIX (BATCH*NB)   // 32768

// ---------------- scratch (bf16) ----------------
__device__ __nv_bfloat16 g_wt[192*256];            // [n][k] transposed Wg|Wf|Wh
__device__ __nv_bfloat16 g_wot[256*128];           // [n][k] transposed Wo
__device__ __nv_bfloat16 g_gb[(size_t)NPIX*32];    // g [row][32]
__device__ __nv_bfloat16 g_fp[BATCH*MB*32];        // f pooled [b*M][32]
__device__ __nv_bfloat16 g_ht[BATCH*128*MB];       // h pooled TRANSPOSED [b][c][m]

// ---------------- helpers ----------------
__device__ __forceinline__ uint32_t packbf(float lo, float hi) {
    __nv_bfloat162 h = __float22bfloat162_rn(make_float2(lo, hi));
    return *reinterpret_cast<uint32_t*>(&h);
}
__device__ __forceinline__ void mma_bf16(float* c,
    uint32_t a0, uint32_t a1, uint32_t a2, uint32_t a3,
    uint32_t b0, uint32_t b1)
{
    asm volatile(
        "mma.sync.aligned.m16n8k16.row.col.f32.bf16.bf16.f32 "
        "{%0,%1,%2,%3},{%4,%5,%6,%7},{%8,%9},{%0,%1,%2,%3};\n"
        : "+f"(c[0]), "+f"(c[1]), "+f"(c[2]), "+f"(c[3])
        : "r"(a0), "r"(a1), "r"(a2), "r"(a3), "r"(b0), "r"(b1));
}
__device__ __forceinline__ void ldm4(uint32_t& r0, uint32_t& r1, uint32_t& r2, uint32_t& r3,
                                     uint32_t addr)
{
    asm volatile("ldmatrix.sync.aligned.m8n8.x4.shared.b16 {%0,%1,%2,%3}, [%4];\n"
                 : "=r"(r0), "=r"(r1), "=r"(r2), "=r"(r3) : "r"(addr));
}
__device__ __forceinline__ void cp16(uint32_t smem_dst, const void* gsrc)
{
    asm volatile("cp.async.cg.shared.global [%0], [%1], 16;\n"
                 :: "r"(smem_dst), "l"(gsrc) : "memory");
}
__device__ __forceinline__ void cp_commit()
{
    asm volatile("cp.async.commit_group;\n" ::: "memory");
}
__device__ __forceinline__ void cp_wait1()
{
    asm volatile("cp.async.wait_group 1;\n" ::: "memory");
}
__device__ __forceinline__ void cp_wait0()
{
    asm volatile("cp.async.wait_group 0;\n" ::: "memory");
}

// ---------------- prep: coalesced smem-tiled transpose + convert ----------------
// 40 blocks x 256 threads. Each block: one [64 k x 32 n] tile.
// blocks 0..3: Wg (g_wt rows 0..31), 4..7: Wf (rows 32..63),
// 8..23: Wh (rows 64..191), 24..39: Wo (g_wot rows 0..255).
__global__ void prep_k(const float* __restrict__ Wf, const float* __restrict__ Wg,
                       const float* __restrict__ Wh, const float* __restrict__ Wo)
{
    __shared__ float ts[32][65];
    const int bid = blockIdx.x, tid = threadIdx.x;

    const float* src; int srcld, srccol, k0, n0, dstld;
    __nv_bfloat16* dst;
    if (bid < 4)       { src = Wg; srcld = 32;  srccol = 0;            k0 = bid*64;        n0 = 0;                dst = g_wt;  dstld = 256; }
    else if (bid < 8)  { src = Wf; srcld = 32;  srccol = 0;            k0 = (bid-4)*64;    n0 = 32;               dst = g_wt;  dstld = 256; }
    else if (bid < 24) { int t = bid-8;  src = Wh; srcld = 128; srccol = (t&3)*32; k0 = (t>>2)*64; n0 = 64 + (t&3)*32; dst = g_wt;  dstld = 256; }
    else               { int t = bid-24; src = Wo; srcld = 256; srccol = (t&7)*32; k0 = (t>>3)*64; n0 = (t&7)*32;      dst = g_wot; dstld = 128; }

    // load [64 k][32 n] tile, coalesced along n
    #pragma unroll
    for (int i = 0; i < 8; i++) {
        int idx = i*256 + tid;
        int kk = idx >> 5, nn = idx & 31;
        ts[nn][kk] = src[(size_t)(k0+kk)*srcld + srccol + nn];
    }
    __syncthreads();

    // store transposed: 32 n-rows x 32 u32 (64 bf16 k), coalesced along k
    uint32_t* dstu = (uint32_t*)dst;
    const int dstld2 = dstld >> 1, k02 = k0 >> 1;
    #pragma unroll
    for (int i = 0; i < 4; i++) {
        int idx = i*256 + tid;
        int nn = idx >> 5, kq = idx & 31;
        dstu[(size_t)(n0+nn)*dstld2 + k02 + kq] = packbf(ts[nn][2*kq], ts[nn][2*kq+1]);
    }
}

// ---------------- projection + fused 2x2 pooling (register-prefetch pipeline) ----------------
__global__ void __launch_bounds__(256) proj_k(const float* __restrict__ X,
    const float* __restrict__ bg, const float* __restrict__ bfv, const float* __restrict__ bh)
{
    __shared__ uint32_t psm[10624];
    uint32_t* Xs = psm;          // [128][20]
    uint32_t* Ws = psm + 2560;   // [192][20]
    uint32_t* Pf = psm;          // [128][17]  (pool phase)
    uint32_t* Ph = psm + 2176;   // [128][66]
    const int tid = threadIdx.x, lane = tid & 31, w = tid >> 5;
    const int gp = lane >> 2, tg = lane & 3, l8 = lane & 7, gq = lane >> 3;
    const int row0 = blockIdx.x * 128;

    float acc[24][4];
    #pragma unroll
    for (int j = 0; j < 24; j++)
        #pragma unroll
        for (int i = 0; i < 4; i++) acc[j][i] = 0.f;

    const uint32_t sX = (uint32_t)__cvta_generic_to_shared(Xs);
    const uint32_t sW = (uint32_t)__cvta_generic_to_shared(Ws);
    const uint32_t aOff = sX + ((16*w + l8 + 8*(gq&1))*40 + 8*(gq>>1))*2;
    const uint32_t bRowOff = (l8 + 8*(gq>>1))*40 + 8*(gq&1);

    const uint4* wsrc = (const uint4*)g_wt;

    float4 xr[4]; uint4 wr[3];
    #pragma unroll
    for (int t = 0; t < 4; t++) {
        int idx = t*256 + tid; int rr = idx >> 3, q = idx & 7;
        xr[t] = *(const float4*)(X + (size_t)(row0+rr)*256 + q*4);
    }
    #pragma unroll
    for (int t = 0; t < 3; t++) {
        int idx = t*256 + tid; int rr = idx >> 2, q = idx & 3;
        wr[t] = wsrc[(size_t)rr*32 + q];
    }

    for (int kc = 0; kc < 256; kc += 32) {
        #pragma unroll
        for (int t = 0; t < 4; t++) {
            int idx = t*256 + tid; int rr = idx >> 3, q = idx & 7;
            Xs[rr*20 + q*2]     = packbf(xr[t].x, xr[t].y);
            Xs[rr*20 + q*2 + 1] = packbf(xr[t].z, xr[t].w);
        }
        #pragma unroll
        for (int t = 0; t < 3; t++) {
            int idx = t*256 + tid; int rr = idx >> 2, q = idx & 3;
            *(uint4*)&Ws[rr*20 + q*4] = wr[t];
        }
        if (kc + 32 < 256) {
            #pragma unroll
            for (int t = 0; t < 4; t++) {
                int idx = t*256 + tid; int rr = idx >> 3, q = idx & 7;
                xr[t] = *(const float4*)(X + (size_t)(row0+rr)*256 + kc + 32 + q*4);
            }
            #pragma unroll
            for (int t = 0; t < 3; t++) {
                int idx = t*256 + tid; int rr = idx >> 2, q = idx & 3;
                wr[t] = wsrc[(size_t)rr*32 + ((kc+32)>>3) + q];
            }
        }
        __syncthreads();
        #pragma unroll
        for (int ks = 0; ks < 2; ks++) {
            uint32_t a0,a1,a2,a3;
            ldm4(a0,a1,a2,a3, aOff + ks*32);
            #pragma unroll
            for (int jp = 0; jp < 12; jp++) {
                uint32_t b0,b1,b2,b3;
                ldm4(b0,b1,b2,b3, sW + (16*jp*40 + bRowOff + ks*16)*2);
                mma_bf16(acc[2*jp],   a0,a1,a2,a3, b0,b1);
                mma_bf16(acc[2*jp+1], a0,a1,a2,a3, b2,b3);
            }
        }
        __syncthreads();
    }

    const int r0l = 16*w + gp, r1l = r0l + 8;
    const int r0g = row0 + r0l, r1g = row0 + r1l;
    uint32_t* gout = (uint32_t*)g_gb;
    #pragma unroll
    for (int j = 0; j < 24; j++) {
        int nb = 8*j, cp = nb + 2*tg;
        if (nb < 32) {
            float b0v = bg[cp], b1v = bg[cp+1];
            gout[(size_t)r0g*16 + (cp>>1)] = packbf(acc[j][0]+b0v, acc[j][1]+b1v);
            gout[(size_t)r1g*16 + (cp>>1)] = packbf(acc[j][2]+b0v, acc[j][3]+b1v);
        } else if (nb < 64) {
            int c = cp - 32;
            float b0v = bfv[c], b1v = bfv[c+1];
            Pf[r0l*17 + (c>>1)] = packbf(acc[j][0]+b0v, acc[j][1]+b1v);
            Pf[r1l*17 + (c>>1)] = packbf(acc[j][2]+b0v, acc[j][3]+b1v);
        } else {
            int c = cp - 64;
            float b0v = bh[c], b1v = bh[c+1];
            Ph[r0l*66 + (c>>1)] = packbf(acc[j][0]+b0v, acc[j][1]+b1v);
            Ph[r1l*66 + (c>>1)] = packbf(acc[j][2]+b0v, acc[j][3]+b1v);
        }
    }
    __syncthreads();

    const int b0i = row0 >> 12;
    const int tpair = (row0 & 4095) >> 7;
    for (int it = tid; it < 512; it += 256) {
        int c2 = it & 15, w2 = it >> 4;
        uint32_t u00 = Pf[(2*w2)*17 + c2];
        uint32_t u01 = Pf[(2*w2+1)*17 + c2];
        uint32_t u10 = Pf[(64+2*w2)*17 + c2];
        uint32_t u11 = Pf[(64+2*w2+1)*17 + c2];
        __nv_bfloat162 v = __hmax2(__hmax2(*(__nv_bfloat162*)&u00, *(__nv_bfloat162*)&u01),
                                   __hmax2(*(__nv_bfloat162*)&u10, *(__nv_bfloat162*)&u11));
        ((uint32_t*)g_fp)[((size_t)b0i*MB + tpair*32 + w2)*16 + c2] = *(uint32_t*)&v;
    }
    for (int it = tid; it < 1024; it += 256) {
        int u = it & 15, c2 = it >> 4;
        int w2a = 2*u, w2b = 2*u + 1;
        uint32_t a0 = Ph[(2*w2a)*66 + c2],    a1 = Ph[(2*w2a+1)*66 + c2];
        uint32_t a2 = Ph[(64+2*w2a)*66 + c2], a3 = Ph[(64+2*w2a+1)*66 + c2];
        __nv_bfloat162 pa = __hmax2(__hmax2(*(__nv_bfloat162*)&a0, *(__nv_bfloat162*)&a1),
                                    __hmax2(*(__nv_bfloat162*)&a2, *(__nv_bfloat162*)&a3));
        uint32_t b0u = Ph[(2*w2b)*66 + c2],    b1u = Ph[(2*w2b+1)*66 + c2];
        uint32_t b2u = Ph[(64+2*w2b)*66 + c2], b3u = Ph[(64+2*w2b+1)*66 + c2];
        __nv_bfloat162 pb = __hmax2(__hmax2(*(__nv_bfloat162*)&b0u, *(__nv_bfloat162*)&b1u),
                                    __hmax2(*(__nv_bfloat162*)&b2u, *(__nv_bfloat162*)&b3u));
        __nv_bfloat162 lo = __halves2bfloat162(__low2bfloat16(pa),  __low2bfloat16(pb));
        __nv_bfloat162 hi = __halves2bfloat162(__high2bfloat16(pa), __high2bfloat16(pb));
        size_t dst = ((size_t)(b0i*128 + 2*c2))*512 + tpair*16 + u;
        ((uint32_t*)g_ht)[dst]       = *(uint32_t*)&lo;
        ((uint32_t*)g_ht)[dst + 512] = *(uint32_t*)&hi;
    }
}

// ---------------- fused attention + output projection ----------------
#define ATTN_SMEM_BYTES 80896

__global__ void __launch_bounds__(256) attn_k(const float* __restrict__ x,
    const float* __restrict__ bo, const float* __restrict__ gamma,
    float* __restrict__ out)
{
    extern __shared__ uint32_t dsm[];
    const int tid = threadIdx.x, lane = tid & 31, w = tid >> 5;
    const int gp = lane >> 2, tg = lane & 3, l8 = lane & 7, gq = lane >> 3;
    const int b = blockIdx.x >> 5, q0 = (blockIdx.x & 31)*128;

    const uint32_t sBase = (uint32_t)__cvta_generic_to_shared(dsm);
    const uint32_t sG = sBase;
    uint32_t sF[3], sH[3];
    #pragma unroll
    for (int i = 0; i < 3; i++) {
        sF[i] = sBase + (2560 + i*1280)*4;
        sH[i] = sBase + (6400 + i*4608)*4;
    }

    const uint32_t* gsrc = (const uint32_t*)g_gb + ((size_t)b*NB + q0)*16;
    const uint32_t* fbase = (const uint32_t*)g_fp + (size_t)b*MB*16;
    const uint32_t* hbase = (const uint32_t*)g_ht + (size_t)b*128*512;

    {
        #pragma unroll
        for (int t = 0; t < 2; t++) {
            int idx = t*256 + tid; int rr = idx >> 2, q4 = idx & 3;
            cp16(sG + (rr*20 + q4*4)*4, gsrc + (size_t)rr*16 + q4*4);
        }
        { int rr = tid >> 2, q4 = tid & 3;
          cp16(sF[0] + (rr*20 + q4*4)*4, fbase + (size_t)rr*16 + q4*4); }
        #pragma unroll
        for (int t = 0; t < 4; t++) {
            int idx = t*256 + tid; int rr = idx >> 3, q4 = idx & 7;
            cp16(sH[0] + (rr*36 + q4*4)*4, hbase + (size_t)rr*512 + q4*4);
        }
        cp_commit();
        { int rr = tid >> 2, q4 = tid & 3;
          cp16(sF[1] + (rr*20 + q4*4)*4, fbase + (size_t)(64+rr)*16 + q4*4); }
        #pragma unroll
        for (int t = 0; t < 4; t++) {
            int idx = t*256 + tid; int rr = idx >> 3, q4 = idx & 7;
            cp16(sH[1] + (rr*36 + q4*4)*4, hbase + (size_t)rr*512 + 32 + q4*4);
        }
        cp_commit();
    }

    const uint32_t aOff = sG + ((16*w + l8 + 8*(gq&1))*40 + 8*(gq>>1))*2;
    const uint32_t bRow40 = (l8 + 8*(gq>>1))*40 + 8*(gq&1);
    const uint32_t bRow72 = (l8 + 8*(gq>>1))*72 + 8*(gq&1);

    float l0v = 0.f, l1v = 0.f;
    float o[16][4];
    #pragma unroll
    for (int j = 0; j < 16; j++)
        #pragma unroll
        for (int i = 0; i < 4; i++) o[j][i] = 0.f;

    #pragma unroll 1
    for (int kt = 0; kt < 16; kt++) {
        const int ib = kt % 3;
        cp_wait1();
        __syncthreads();

        {
            const int kt2 = kt + 2;
            if (kt2 < 16) {
                const int ib2 = kt2 % 3;
                int rr = tid >> 2, q4 = tid & 3;
                cp16(sF[ib2] + (rr*20 + q4*4)*4, fbase + (size_t)(kt2*64 + rr)*16 + q4*4);
                #pragma unroll
                for (int t = 0; t < 4; t++) {
                    int idx = t*256 + tid; int hr = idx >> 3, hq = idx & 7;
                    cp16(sH[ib2] + (hr*36 + hq*4)*4, hbase + (size_t)hr*512 + kt2*32 + hq*4);
                }
            }
            cp_commit();
        }

        float s[8][4];
        #pragma unroll
        for (int j = 0; j < 8; j++)
            #pragma unroll
            for (int i = 0; i < 4; i++) s[j][i] = 0.f;
        #pragma unroll
        for (int ks = 0; ks < 2; ks++) {
            uint32_t a0,a1,a2,a3;
            ldm4(a0,a1,a2,a3, aOff + ks*32);
            #pragma unroll
            for (int jp = 0; jp < 4; jp++) {
                uint32_t b0,b1,b2,b3;
                ldm4(b0,b1,b2,b3, sF[ib] + (16*jp*40 + bRow40 + ks*16)*2);
                mma_bf16(s[2*jp],   a0,a1,a2,a3, b0,b1);
                mma_bf16(s[2*jp+1], a0,a1,a2,a3, b2,b3);
            }
        }

        // no-max softmax
        {
            float rs0 = 0.f, rs1 = 0.f;
            #pragma unroll
            for (int j = 0; j < 8; j++) {
                s[j][0] = __expf(s[j][0]);
                s[j][1] = __expf(s[j][1]);
                rs0 += s[j][0] + s[j][1];
                s[j][2] = __expf(s[j][2]);
                s[j][3] = __expf(s[j][3]);
                rs1 += s[j][2] + s[j][3];
            }
            rs0 += __shfl_xor_sync(0xffffffffu, rs0, 1);
            rs0 += __shfl_xor_sync(0xffffffffu, rs0, 2);
            rs1 += __shfl_xor_sync(0xffffffffu, rs1, 1);
            rs1 += __shfl_xor_sync(0xffffffffu, rs1, 2);
            l0v += rs0;
            l1v += rs1;
        }

        uint32_t pa[4][4];
        #pragma unroll
        for (int ks = 0; ks < 4; ks++) {
            pa[ks][0] = packbf(s[2*ks][0],   s[2*ks][1]);
            pa[ks][1] = packbf(s[2*ks][2],   s[2*ks][3]);
            pa[ks][2] = packbf(s[2*ks+1][0], s[2*ks+1][1]);
            pa[ks][3] = packbf(s[2*ks+1][2], s[2*ks+1][3]);
        }

        #pragma unroll
        for (int jp = 0; jp < 8; jp++) {
            #pragma unroll
            for (int ks = 0; ks < 4; ks++) {
                uint32_t b0,b1,b2,b3;
                ldm4(b0,b1,b2,b3, sH[ib] + (16*jp*72 + bRow72 + ks*16)*2);
                mma_bf16(o[2*jp],   pa[ks][0],pa[ks][1],pa[ks][2],pa[ks][3], b0,b1);
                mma_bf16(o[2*jp+1], pa[ks][0],pa[ks][1],pa[ks][2],pa[ks][3], b2,b3);
            }
        }
    }

    // ---- fused output projection ----
    const float inv0 = 1.f / l0v, inv1 = 1.f / l1v;
    uint32_t oa[8][4];
    #pragma unroll
    for (int ks = 0; ks < 8; ks++) {
        oa[ks][0] = packbf(o[2*ks][0]*inv0,   o[2*ks][1]*inv0);
        oa[ks][1] = packbf(o[2*ks][2]*inv1,   o[2*ks][3]*inv1);
        oa[ks][2] = packbf(o[2*ks+1][0]*inv0, o[2*ks+1][1]*inv0);
        oa[ks][3] = packbf(o[2*ks+1][2]*inv1, o[2*ks+1][3]*inv1);
    }

    __syncthreads();   // all warps done with F/H smem before Wo overwrite

    // Wo^T tile in two halves: rows 0..127 (pass 0), rows 128..255 (pass 1)
    const uint32_t* wsrc = (const uint32_t*)g_wot;
    #pragma unroll
    for (int t = 0; t < 8; t++) {
        int idx = t*256 + tid; int rr = idx >> 4, q4 = idx & 15;
        cp16(sBase + (rr*68 + q4*4)*4, wsrc + (size_t)rr*64 + q4*4);
    }
    cp_commit();
    #pragma unroll
    for (int t = 0; t < 8; t++) {
        int idx = t*256 + tid; int rr = (idx >> 4) + 128, q4 = idx & 15;
        cp16(sBase + (rr*68 + q4*4)*4, wsrc + (size_t)rr*64 + q4*4);
    }
    cp_commit();

    const uint32_t bRow136 = (l8 + 8*(gq>>1))*136 + 8*(gq&1);
    const float gm = gamma[0];
    const int r0g = b*NB + q0 + 16*w + gp, r1g = r0g + 8;

    cp_wait1();        // half 0 resident
    __syncthreads();

    #pragma unroll 1
    for (int pass = 0; pass < 2; pass++) {
        if (pass == 1) {
            cp_wait0();    // half 1 resident
            __syncthreads();
        }
        float acc[16][4];
        #pragma unroll
        for (int j = 0; j < 16; j++)
            #pragma unroll
            for (int i = 0; i < 4; i++) acc[j][i] = 0.f;

        #pragma unroll
        for (int ks = 0; ks < 8; ks++) {
            #pragma unroll
            for (int jp = 0; jp < 8; jp++) {
                uint32_t b0,b1,b2,b3;
                ldm4(b0,b1,b2,b3, sBase + ((128*pass + 16*jp)*136 + bRow136 + ks*16)*2);
                mma_bf16(acc[2*jp],   oa[ks][0],oa[ks][1],oa[ks][2],oa[ks][3], b0,b1);
                mma_bf16(acc[2*jp+1], oa[ks][0],oa[ks][1],oa[ks][2],oa[ks][3], b2,b3);
            }
        }

        #pragma unroll
        for (int j = 0; j < 16; j++) {
            int col = 128*pass + 8*j + 2*tg;
            float b0v = bo[col], b1v = bo[col+1];
            float2 xv0 = *(const float2*)(x + (size_t)r0g*256 + col);
            float2 ov0 = make_float2(gm*(acc[j][0]+b0v) + xv0.x, gm*(acc[j][1]+b1v) + xv0.y);
            *(float2*)(out + (size_t)r0g*256 + col) = ov0;
            float2 xv1 = *(const float2*)(x + (size_t)r1g*256 + col);
            float2 ov1 = make_float2(gm*(acc[j][2]+b0v) + xv1.x, gm*(acc[j][3]+b1v) + xv1.y);
            *(float2*)(out + (size_t)r1g*256 + col) = ov1;
        }
    }
}

// ---------------- launch ----------------
extern "C" void kernel_launch(void* const* d_in, const int* in_sizes, int n_in,
                              void* d_out, int out_size)
{
    (void)in_sizes; (void)n_in; (void)out_size;
    const float* x     = (const float*)d_in[0];
    const float* Wf    = (const float*)d_in[1];
    const float* bfv   = (const float*)d_in[2];
    const float* Wg    = (const float*)d_in[3];
    const float* bg    = (const float*)d_in[4];
    const float* Wh    = (const float*)d_in[5];
    const float* bh    = (const float*)d_in[6];
    const float* Wo    = (const float*)d_in[7];
    const float* bo    = (const float*)d_in[8];
    const float* gamma = (const float*)d_in[9];
    float* out = (float*)d_out;

    static bool attr_set = false;
    if (!attr_set) {
        cudaFuncSetAttribute(attn_k, cudaFuncAttributeMaxDynamicSharedMemorySize,
                             ATTN_SMEM_BYTES);
        attr_set = true;
    }

    prep_k<<<40, 256>>>(Wf, Wg, Wh, Wo);
    proj_k<<<NPIX/128, 256>>>(x, bg, bfv, bh);
    attn_k<<<NPIX/128, 256, ATTN_SMEM_BYTES>>>(x, bo, gamma, out);
}